// round 1
// baseline (speedup 1.0000x reference)
#include <cuda_runtime.h>
#include <cuda_bf16.h>
#include <math.h>

// Problem constants
#define BB 128
#define NN 49
#define CC 2048
#define DD 512
#define EE 512
#define VOC 10000
#define TT 20

// ---------------- scratch (device globals; no allocation allowed) ----------------
__device__ float g_mean[BB * CC];                 // [128,2048]
__device__ float g_Vf[BB * NN * DD];              // [128,49,512]
__device__ float g_zbase[BB * NN * NN];           // [128,49,49]
__device__ float g_vg[BB * DD];
__device__ float g_h[BB * DD];
__device__ float g_m[BB * DD];
__device__ float g_we[TT * BB * EE];              // [t][b][e]
__device__ float g_weWih[TT * BB * 4 * DD];       // [t][b][2048]
__device__ float g_vgWih[BB * 4 * DD];            // [b][2048]
__device__ float g_weWx[TT * BB * DD];            // [t][b][512]
__device__ float g_vgWx[BB * DD];
__device__ float g_WhhCat[(4 * DD + DD) * DD];    // [2560,512]
__device__ float g_gcat[BB * (4 * DD + DD)];      // [128,2560]
__device__ float g_a[BB * DD];
__device__ float g_H[BB * DD];
__device__ float g_s[BB * DD];
__device__ float g_gH[BB * NN];
__device__ float g_sWs[BB * NN];
__device__ float g_ctxH[BB * DD];
__device__ float g_out[TT * BB * DD];             // [t][b][512]
__device__ float g_logits[(size_t)TT * BB * VOC]; // [t*128+b][10000]

// ---------------- generic NT GEMM: C[m,n] = sum_k A[m,k]*B[n,k] (+bias, act) ----
// act: 0 none, 1 relu, 2 tanh
template <int BM, int BN, int BK, int TM, int TN>
__global__ void gemm_nt(const float* __restrict__ A, int lda,
                        const float* __restrict__ Bm, int ldb,
                        const float* __restrict__ bias,
                        float* __restrict__ C, int ldc,
                        int M, int N, int K, int act,
                        long long sA, long long sB, long long sC)
{
    constexpr int THREADS = (BM / TM) * (BN / TN);
    __shared__ float As[BK][BM + 4];
    __shared__ float Bs[BK][BN + 4];

    A += (long long)blockIdx.z * sA;
    Bm += (long long)blockIdx.z * sB;
    C += (long long)blockIdx.z * sC;

    const int tid = threadIdx.x;
    const int bm0 = blockIdx.y * BM;
    const int bn0 = blockIdx.x * BN;
    const int tm = (tid / (BN / TN)) * TM;
    const int tn = (tid % (BN / TN)) * TN;

    float acc[TM][TN];
#pragma unroll
    for (int i = 0; i < TM; i++)
#pragma unroll
        for (int j = 0; j < TN; j++) acc[i][j] = 0.f;

    for (int k0 = 0; k0 < K; k0 += BK) {
        // load A tile (BM x BK) as float4 along K
#pragma unroll
        for (int i = tid; i < BM * (BK / 4); i += THREADS) {
            int row = i / (BK / 4);
            int kc = i % (BK / 4);
            int gm = bm0 + row;
            int gk = k0 + kc * 4;
            float4 v = make_float4(0.f, 0.f, 0.f, 0.f);
            if (gm < M) {
                if (gk + 3 < K) {
                    v = *reinterpret_cast<const float4*>(A + (size_t)gm * lda + gk);
                } else {
                    float t0 = (gk + 0 < K) ? A[(size_t)gm * lda + gk + 0] : 0.f;
                    float t1 = (gk + 1 < K) ? A[(size_t)gm * lda + gk + 1] : 0.f;
                    float t2 = (gk + 2 < K) ? A[(size_t)gm * lda + gk + 2] : 0.f;
                    float t3 = (gk + 3 < K) ? A[(size_t)gm * lda + gk + 3] : 0.f;
                    v = make_float4(t0, t1, t2, t3);
                }
            }
            As[kc * 4 + 0][row] = v.x; As[kc * 4 + 1][row] = v.y;
            As[kc * 4 + 2][row] = v.z; As[kc * 4 + 3][row] = v.w;
        }
        // load B tile (BN x BK)
#pragma unroll
        for (int i = tid; i < BN * (BK / 4); i += THREADS) {
            int row = i / (BK / 4);
            int kc = i % (BK / 4);
            int gn = bn0 + row;
            int gk = k0 + kc * 4;
            float4 v = make_float4(0.f, 0.f, 0.f, 0.f);
            if (gn < N) {
                if (gk + 3 < K) {
                    v = *reinterpret_cast<const float4*>(Bm + (size_t)gn * ldb + gk);
                } else {
                    float t0 = (gk + 0 < K) ? Bm[(size_t)gn * ldb + gk + 0] : 0.f;
                    float t1 = (gk + 1 < K) ? Bm[(size_t)gn * ldb + gk + 1] : 0.f;
                    float t2 = (gk + 2 < K) ? Bm[(size_t)gn * ldb + gk + 2] : 0.f;
                    float t3 = (gk + 3 < K) ? Bm[(size_t)gn * ldb + gk + 3] : 0.f;
                    v = make_float4(t0, t1, t2, t3);
                }
            }
            Bs[kc * 4 + 0][row] = v.x; Bs[kc * 4 + 1][row] = v.y;
            Bs[kc * 4 + 2][row] = v.z; Bs[kc * 4 + 3][row] = v.w;
        }
        __syncthreads();

#pragma unroll
        for (int k = 0; k < BK; k++) {
            float ra[TM], rb[TN];
#pragma unroll
            for (int i = 0; i < TM; i++) ra[i] = As[k][tm + i];
#pragma unroll
            for (int j = 0; j < TN; j++) rb[j] = Bs[k][tn + j];
#pragma unroll
            for (int i = 0; i < TM; i++)
#pragma unroll
                for (int j = 0; j < TN; j++) acc[i][j] += ra[i] * rb[j];
        }
        __syncthreads();
    }

#pragma unroll
    for (int i = 0; i < TM; i++) {
        int gm = bm0 + tm + i;
        if (gm >= M) continue;
#pragma unroll
        for (int j = 0; j < TN; j++) {
            int gn = bn0 + tn + j;
            if (gn >= N) continue;
            float v = acc[i][j];
            if (bias) v += bias[gn];
            if (act == 1) v = fmaxf(v, 0.f);
            else if (act == 2) v = tanhf(v);
            C[(size_t)gm * ldc + gn] = v;
        }
    }
}

// ---------------- small helper kernels ----------------
__global__ void mean_kernel(const float* __restrict__ x, float* __restrict__ mean)
{
    int idx = blockIdx.x * blockDim.x + threadIdx.x; // B*C
    if (idx >= BB * CC) return;
    int b = idx / CC, c = idx % CC;
    float acc = 0.f;
    const float* p = x + (size_t)b * NN * CC + c;
#pragma unroll 7
    for (int n = 0; n < NN; n++) acc += p[(size_t)n * CC];
    mean[idx] = acc * (1.f / (float)NN);
}

__global__ void we_build(const int* __restrict__ target, const float* __restrict__ emb,
                         float* __restrict__ we)
{
    int idx = blockIdx.x * blockDim.x + threadIdx.x; // T*B*E
    if (idx >= TT * BB * EE) return;
    int e = idx & (EE - 1);
    int tb = idx >> 9;
    int b = tb % BB;
    int t = tb / BB;
    float v = 0.f;
    if (t > 0) {
        int tok = target[b * TT + (t - 1)];
        v = emb[(size_t)tok * EE + e];
    }
    we[idx] = v;
}

__global__ void cat_whh(const float* __restrict__ Whh, const float* __restrict__ Wh2,
                        float* __restrict__ Wcat)
{
    int idx = blockIdx.x * blockDim.x + threadIdx.x; // 2560*512
    if (idx >= (4 * DD + DD) * DD) return;
    int r = idx >> 9;
    Wcat[idx] = (r < 4 * DD) ? Whh[idx] : Wh2[idx - 4 * DD * DD];
}

__device__ __forceinline__ float sigmoidf(float x) { return 1.f / (1.f + expf(-x)); }

__global__ void lstm_elem(const float* __restrict__ bih, const float* __restrict__ bhh,
                          int t)
{
    int idx = blockIdx.x * blockDim.x + threadIdx.x; // B*D = 65536
    if (idx >= BB * DD) return;
    int b = idx >> 9, d = idx & (DD - 1);
    const float* gr = g_gcat + (size_t)b * (4 * DD + DD);
    const float* xr = g_weWih + ((size_t)(t * BB + b)) * (4 * DD);
    const float* vr = g_vgWih + (size_t)b * (4 * DD);

    float gi = gr[d] + xr[d] + vr[d] + bih[d] + bhh[d];
    float gf = gr[DD + d] + xr[DD + d] + vr[DD + d] + bih[DD + d] + bhh[DD + d];
    float gg = gr[2 * DD + d] + xr[2 * DD + d] + vr[2 * DD + d] + bih[2 * DD + d] + bhh[2 * DD + d];
    float go = gr[3 * DD + d] + xr[3 * DD + d] + vr[3 * DD + d] + bih[3 * DD + d] + bhh[3 * DD + d];

    float i_ = sigmoidf(gi);
    float f_ = sigmoidf(gf);
    float m2 = f_ * g_m[idx] + i_ * tanhf(gg);
    float tm2 = tanhf(m2);
    float h2 = sigmoidf(go) * tm2;

    float gt = sigmoidf(g_weWx[(size_t)(t * BB + b) * DD + d] + g_vgWx[idx] + gr[4 * DD + d]);

    g_h[idx] = h2;
    g_m[idx] = m2;
    g_a[idx] = gt * tm2;
}

// gH = H @ Wg^T, sWs = s @ Ws^T   (N=49, K=512)
__global__ void proj49(const float* __restrict__ Wg, const float* __restrict__ Ws)
{
    int z = blockIdx.y;
    int idx = blockIdx.x * blockDim.x + threadIdx.x;
    if (idx >= BB * NN) return;
    int b = idx / NN, n = idx % NN;
    const float* a = (z ? g_s : g_H) + (size_t)b * DD;
    const float* w = (z ? Ws : Wg) + (size_t)n * DD;
    float acc = 0.f;
#pragma unroll 8
    for (int k = 0; k < DD; k += 4) {
        float4 av = *reinterpret_cast<const float4*>(a + k);
        float4 wv = *reinterpret_cast<const float4*>(w + k);
        acc += av.x * wv.x + av.y * wv.y + av.z * wv.z + av.w * wv.w;
    }
    (z ? g_sWs : g_gH)[idx] = acc;
}

// attention + context + (H + ctx); writes attn slice of d_out
__global__ void attn_step(const float* __restrict__ wh, float* __restrict__ out_attn, int t)
{
    int b = blockIdx.x;
    int tid = threadIdx.x;
    __shared__ float gHs[NN], whs[NN], zs[NN + 1], alphas[NN + 1];
    if (tid < NN) { gHs[tid] = g_gH[b * NN + tid]; whs[tid] = wh[tid]; }
    __syncthreads();

    if (tid < NN) {
        const float* zb = g_zbase + ((size_t)b * NN + tid) * NN;
        float acc = 0.f;
        for (int k = 0; k < NN; k++) acc += tanhf(zb[k] + gHs[k]) * whs[k];
        zs[tid] = acc;
    } else if (tid == NN) {
        const float* sw = g_sWs + (size_t)b * NN;
        float acc = 0.f;
        for (int k = 0; k < NN; k++) acc += tanhf(sw[k] + gHs[k]) * whs[k];
        zs[NN] = acc;
    }
    __syncthreads();

    if (tid == 0) {
        float mx = -1e30f;
        for (int i = 0; i <= NN; i++) mx = fmaxf(mx, zs[i]);
        float sum = 0.f;
        for (int i = 0; i <= NN; i++) { float e = expf(zs[i] - mx); alphas[i] = e; sum += e; }
        float inv = 1.f / sum;
        for (int i = 0; i <= NN; i++) alphas[i] *= inv;
    }
    __syncthreads();

    if (tid < NN) out_attn[((size_t)b * TT + t) * NN + tid] = alphas[tid];

    for (int d = tid; d < DD; d += blockDim.x) {
        float acc = alphas[NN] * g_s[(size_t)b * DD + d];
        const float* vf = g_Vf + (size_t)b * NN * DD + d;
#pragma unroll 7
        for (int n = 0; n < NN; n++) acc += alphas[n] * vf[(size_t)n * DD];
        g_ctxH[(size_t)b * DD + d] = acc + g_H[(size_t)b * DD + d];
    }
}

__global__ void logsoftmax_kernel(float* __restrict__ out)
{
    int r = blockIdx.x;          // r = t*128 + b
    int t = r / BB, b = r % BB;
    const float* row = g_logits + (size_t)r * VOC;
    __shared__ float red[256];
    float mx = -1e30f;
    for (int v = threadIdx.x; v < VOC; v += 256) mx = fmaxf(mx, row[v]);
    red[threadIdx.x] = mx; __syncthreads();
    for (int s = 128; s > 0; s >>= 1) {
        if (threadIdx.x < s) red[threadIdx.x] = fmaxf(red[threadIdx.x], red[threadIdx.x + s]);
        __syncthreads();
    }
    mx = red[0]; __syncthreads();
    float sum = 0.f;
    for (int v = threadIdx.x; v < VOC; v += 256) sum += expf(row[v] - mx);
    red[threadIdx.x] = sum; __syncthreads();
    for (int s = 128; s > 0; s >>= 1) {
        if (threadIdx.x < s) red[threadIdx.x] += red[threadIdx.x + s];
        __syncthreads();
    }
    float lse = mx + logf(red[0]);
    float* orow = out + ((size_t)b * TT + t) * VOC;
    for (int v = threadIdx.x; v < VOC; v += 256) orow[v] = row[v] - lse;
}

// ---------------- host-side launch helpers ----------------
static inline void gemm_big(const float* A, int lda, const float* Bm, int ldb,
                            const float* bias, float* C, int ldc,
                            int M, int N, int K, int act)
{
    dim3 grid((N + 127) / 128, (M + 127) / 128, 1);
    gemm_nt<128, 128, 16, 8, 8><<<grid, 256>>>(A, lda, Bm, ldb, bias, C, ldc, M, N, K, act, 0, 0, 0);
}

static inline void gemm_small(const float* A, int lda, const float* Bm, int ldb,
                              const float* bias, float* C, int ldc,
                              int M, int N, int K, int act,
                              int batch = 1, long long sA = 0, long long sB = 0, long long sC = 0)
{
    dim3 grid((N + 63) / 64, (M + 63) / 64, batch);
    gemm_nt<64, 64, 16, 4, 4><<<grid, 256>>>(A, lda, Bm, ldb, bias, C, ldc, M, N, K, act, sA, sB, sC);
}

extern "C" void kernel_launch(void* const* d_in, const int* in_sizes, int n_in,
                              void* d_out, int out_size)
{
    const float* image = (const float*)d_in[0];
    const int*   target = (const int*)d_in[1];
    const float* emb = (const float*)d_in[2];
    const float* Wa = (const float*)d_in[3];  const float* ba = (const float*)d_in[4];
    const float* Wb = (const float*)d_in[5];  const float* bb = (const float*)d_in[6];
    const float* Whi = (const float*)d_in[7]; const float* bhi = (const float*)d_in[8];
    const float* Wmi = (const float*)d_in[9]; const float* bmi = (const float*)d_in[10];
    const float* Wih = (const float*)d_in[11]; const float* bih = (const float*)d_in[12];
    const float* Whh = (const float*)d_in[13]; const float* bhh = (const float*)d_in[14];
    const float* Wv = (const float*)d_in[15];
    const float* Wg = (const float*)d_in[16];
    const float* wh = (const float*)d_in[17];
    const float* WH = (const float*)d_in[18];
    const float* Wx = (const float*)d_in[19];
    const float* Wh2 = (const float*)d_in[20];
    const float* Ws = (const float*)d_in[21];
    const float* Wc = (const float*)d_in[22]; const float* bc = (const float*)d_in[23];
    const float* Wfc = (const float*)d_in[24]; const float* bfc = (const float*)d_in[25];
    const float* Wp = (const float*)d_in[26]; const float* bp = (const float*)d_in[27];

    float* out = (float*)d_out;
    float* out_attn = out + (size_t)BB * TT * VOC;

    // resolve device-global addresses
    float *p_mean, *p_Vf, *p_zbase, *p_vg, *p_h, *p_m, *p_we, *p_weWih, *p_vgWih;
    float *p_weWx, *p_vgWx, *p_WhhCat, *p_gcat, *p_a, *p_H, *p_s, *p_ctxH, *p_out, *p_logits;
    cudaGetSymbolAddress((void**)&p_mean, g_mean);
    cudaGetSymbolAddress((void**)&p_Vf, g_Vf);
    cudaGetSymbolAddress((void**)&p_zbase, g_zbase);
    cudaGetSymbolAddress((void**)&p_vg, g_vg);
    cudaGetSymbolAddress((void**)&p_h, g_h);
    cudaGetSymbolAddress((void**)&p_m, g_m);
    cudaGetSymbolAddress((void**)&p_we, g_we);
    cudaGetSymbolAddress((void**)&p_weWih, g_weWih);
    cudaGetSymbolAddress((void**)&p_vgWih, g_vgWih);
    cudaGetSymbolAddress((void**)&p_weWx, g_weWx);
    cudaGetSymbolAddress((void**)&p_vgWx, g_vgWx);
    cudaGetSymbolAddress((void**)&p_WhhCat, g_WhhCat);
    cudaGetSymbolAddress((void**)&p_gcat, g_gcat);
    cudaGetSymbolAddress((void**)&p_a, g_a);
    cudaGetSymbolAddress((void**)&p_H, g_H);
    cudaGetSymbolAddress((void**)&p_s, g_s);
    cudaGetSymbolAddress((void**)&p_ctxH, g_ctxH);
    cudaGetSymbolAddress((void**)&p_out, g_out);
    cudaGetSymbolAddress((void**)&p_logits, g_logits);
    (void)p_a; (void)p_H; (void)p_s; (void)p_ctxH; // accessed via globals in kernels

    // ---- precompute phase ----
    mean_kernel<<<(BB * CC + 255) / 256, 256>>>(image, p_mean);
    // Vf = relu(image @ Wa^T + ba)  [6272,512]
    gemm_big(image, CC, Wa, CC, ba, p_Vf, DD, BB * NN, DD, CC, 1);
    // vg/h0/m0
    gemm_small(p_mean, CC, Wb, CC, bb, p_vg, DD, BB, DD, CC, 1);
    gemm_small(p_mean, CC, Whi, CC, bhi, p_h, DD, BB, DD, CC, 1);
    gemm_small(p_mean, CC, Wmi, CC, bmi, p_m, DD, BB, DD, CC, 1);
    // zbase: batched over B: Vf_b[49,512] @ Wv[49,512]^T
    gemm_small(p_Vf, DD, Wv, DD, nullptr, p_zbase, NN, NN, NN, DD, 0,
               BB, (long long)NN * DD, 0, (long long)NN * NN);
    // embeddings (shifted)
    we_build<<<(TT * BB * EE + 255) / 256, 256>>>(target, emb, p_we);
    // batched input projections
    gemm_big(p_we, EE, Wih + DD, DD + EE, nullptr, p_weWih, 4 * DD, TT * BB, 4 * DD, EE, 0);
    gemm_small(p_vg, DD, Wih, DD + EE, nullptr, p_vgWih, 4 * DD, BB, 4 * DD, DD, 0);
    gemm_big(p_we, EE, Wx + DD, DD + EE, nullptr, p_weWx, DD, TT * BB, DD, EE, 0);
    gemm_small(p_vg, DD, Wx, DD + EE, nullptr, p_vgWx, DD, BB, DD, DD, 0);
    // concat [Whh; Wh2]
    cat_whh<<<((4 * DD + DD) * DD + 255) / 256, 256>>>(Whh, Wh2, p_WhhCat);

    // ---- sequential recurrence ----
    for (int t = 0; t < TT; t++) {
        // gcat = h @ [Whh;Wh2]^T  [128,2560]
        gemm_small(p_h, DD, p_WhhCat, DD, nullptr, p_gcat, 4 * DD + DD, BB, 4 * DD + DD, DD, 0);
        lstm_elem<<<(BB * DD + 255) / 256, 256>>>(bih, bhh, t);
        // H = relu(h2 @ WH^T); s = relu(a @ Wc^T + bc)
        gemm_small(p_h, DD, WH, DD, nullptr, p_H, DD, BB, DD, DD, 1);
        gemm_small(p_a, DD, Wc, DD, bc, p_s, DD, BB, DD, DD, 1);
        // gH, sWs
        {
            dim3 grid((BB * NN + 255) / 256, 2);
            proj49<<<grid, 256>>>(Wg, Ws);
        }
        attn_step<<<BB, 256>>>(wh, out_attn, t);
        // out_t = tanh((H+ctx) @ Wfc^T + bfc)
        gemm_small(p_ctxH, DD, Wfc, DD, bfc, p_out + (size_t)t * BB * DD, DD, BB, DD, DD, 2);
    }

    // ---- logits + log_softmax ----
    gemm_big(p_out, DD, Wp, DD, bp, p_logits, VOC, TT * BB, VOC, DD, 0);
    logsoftmax_kernel<<<TT * BB, 256>>>(out);
}

// round 2
// speedup vs baseline: 2.2241x; 2.2241x over previous
#include <cuda_runtime.h>
#include <cuda_bf16.h>
#include <math.h>

#define BB 128
#define NN 49
#define CC 2048
#define DD 512
#define EE 512
#define VOC 10000
#define TT 20
#define RR (TT * BB)   // 2560 batched rows

// ---------------- scratch (device globals) ----------------
__device__ float g_mean[BB * CC];
__device__ float g_Vf[BB * NN * DD];
__device__ float g_zbase[BB * NN * NN];
__device__ float g_Wcat[3 * DD * CC];             // [Wb;Whi;Wmi] cat rows
__device__ float g_init[BB * 3 * DD];             // [128,1536] relu outputs
__device__ float g_vg[BB * DD];
__device__ float g_m[BB * DD];
__device__ float g_hseq[(TT + 1) * BB * DD];      // h_0..h_20
__device__ float g_tm[RR * DD];                   // tanh(m2) per step
__device__ float g_we[RR * EE];
__device__ float g_xg[RR * 4 * DD];               // x@Wih^T + vgWih + bih + bhh
__device__ float g_vgWih[BB * 4 * DD];
__device__ float g_xx[RR * DD];                   // x@Wx^T (+vgWx folded)
__device__ float g_vgWx[BB * DD];
__device__ float g_G1[RR * DD];                   // hp@Wh2^T
__device__ float g_a[RR * DD];
__device__ float g_H[RR * DD];
__device__ float g_s[RR * DD];
__device__ float g_gH[RR * NN];
__device__ float g_sWs[RR * NN];
__device__ float g_ctxH[RR * DD];
__device__ float g_out[RR * DD];
__device__ float g_logits[(size_t)RR * VOC];

__device__ __forceinline__ float sigmoidf_(float x) { return 1.f / (1.f + expf(-x)); }

// ---------------- generic NT GEMM ----------------
// C[m,n] = sum_k A[m,k]*B[n,k] (+bias, act) ; act: 0 none, 1 relu, 2 tanh
template <int BM, int BN, int BK, int TM, int TN>
__global__ void gemm_nt(const float* __restrict__ A, int lda,
                        const float* __restrict__ Bm, int ldb,
                        const float* __restrict__ bias,
                        float* __restrict__ C, int ldc,
                        int M, int N, int K, int act,
                        long long sA, long long sB, long long sC)
{
    constexpr int THREADS = (BM / TM) * (BN / TN);
    __shared__ float As[BK][BM + 4];
    __shared__ float Bs[BK][BN + 4];

    A += (long long)blockIdx.z * sA;
    Bm += (long long)blockIdx.z * sB;
    C += (long long)blockIdx.z * sC;

    const int tid = threadIdx.x;
    const int bm0 = blockIdx.y * BM;
    const int bn0 = blockIdx.x * BN;
    const int tm = (tid / (BN / TN)) * TM;
    const int tn = (tid % (BN / TN)) * TN;

    float acc[TM][TN];
#pragma unroll
    for (int i = 0; i < TM; i++)
#pragma unroll
        for (int j = 0; j < TN; j++) acc[i][j] = 0.f;

    for (int k0 = 0; k0 < K; k0 += BK) {
#pragma unroll
        for (int i = tid; i < BM * (BK / 4); i += THREADS) {
            int row = i / (BK / 4);
            int kc = i % (BK / 4);
            int gm = bm0 + row;
            int gk = k0 + kc * 4;
            float4 v = make_float4(0.f, 0.f, 0.f, 0.f);
            if (gm < M) v = *reinterpret_cast<const float4*>(A + (size_t)gm * lda + gk);
            As[kc * 4 + 0][row] = v.x; As[kc * 4 + 1][row] = v.y;
            As[kc * 4 + 2][row] = v.z; As[kc * 4 + 3][row] = v.w;
        }
#pragma unroll
        for (int i = tid; i < BN * (BK / 4); i += THREADS) {
            int row = i / (BK / 4);
            int kc = i % (BK / 4);
            int gn = bn0 + row;
            int gk = k0 + kc * 4;
            float4 v = make_float4(0.f, 0.f, 0.f, 0.f);
            if (gn < N) v = *reinterpret_cast<const float4*>(Bm + (size_t)gn * ldb + gk);
            Bs[kc * 4 + 0][row] = v.x; Bs[kc * 4 + 1][row] = v.y;
            Bs[kc * 4 + 2][row] = v.z; Bs[kc * 4 + 3][row] = v.w;
        }
        __syncthreads();

#pragma unroll
        for (int k = 0; k < BK; k++) {
            float ra[TM], rb[TN];
#pragma unroll
            for (int i = 0; i < TM; i++) ra[i] = As[k][tm + i];
#pragma unroll
            for (int j = 0; j < TN; j++) rb[j] = Bs[k][tn + j];
#pragma unroll
            for (int i = 0; i < TM; i++)
#pragma unroll
                for (int j = 0; j < TN; j++) acc[i][j] += ra[i] * rb[j];
        }
        __syncthreads();
    }

#pragma unroll
    for (int i = 0; i < TM; i++) {
        int gm = bm0 + tm + i;
        if (gm >= M) continue;
#pragma unroll
        for (int j = 0; j < TN; j++) {
            int gn = bn0 + tn + j;
            if (gn >= N) continue;
            float v = acc[i][j];
            if (bias) v += bias[gn];
            if (act == 1) v = fmaxf(v, 0.f);
            else if (act == 2) v = tanhf(v);
            C[(size_t)gm * ldc + gn] = v;
        }
    }
}

// ---------------- fused LSTM step: gates GEMM + elementwise ----------------
// grid (32, 2), block 256. Tile: 64 b rows × [16 d × 4 gates] cols, K=512.
__global__ void lstm_step(const float* __restrict__ Whh,   // [2048,512]
                          const float* __restrict__ xg,    // [128,2048] (this t)
                          const float* __restrict__ h_prev,// [128,512]
                          float* __restrict__ m,           // [128,512] in-place
                          float* __restrict__ h_out,       // [128,512]
                          float* __restrict__ tm_out)      // [128,512]
{
    __shared__ float As[16][68];
    __shared__ float Bs[16][68];
    __shared__ float Cs[64][68];

    const int tid = threadIdx.x;
    const int b0 = blockIdx.y * 64;
    const int d0 = blockIdx.x * 16;
    const int tm_ = (tid / 16) * 4;
    const int tn_ = (tid % 16) * 4;

    float acc[4][4] = {};

    for (int k0 = 0; k0 < DD; k0 += 16) {
        {
            int row = tid / 4, kc = tid % 4;
            float4 v = *reinterpret_cast<const float4*>(h_prev + (size_t)(b0 + row) * DD + k0 + kc * 4);
            As[kc * 4 + 0][row] = v.x; As[kc * 4 + 1][row] = v.y;
            As[kc * 4 + 2][row] = v.z; As[kc * 4 + 3][row] = v.w;
        }
        {
            int c = tid / 4, kc = tid % 4;
            int j = (c >> 4) * DD + d0 + (c & 15);
            float4 v = *reinterpret_cast<const float4*>(Whh + (size_t)j * DD + k0 + kc * 4);
            Bs[kc * 4 + 0][c] = v.x; Bs[kc * 4 + 1][c] = v.y;
            Bs[kc * 4 + 2][c] = v.z; Bs[kc * 4 + 3][c] = v.w;
        }
        __syncthreads();
#pragma unroll
        for (int k = 0; k < 16; k++) {
            float ra[4], rb[4];
#pragma unroll
            for (int i = 0; i < 4; i++) ra[i] = As[k][tm_ + i];
#pragma unroll
            for (int j = 0; j < 4; j++) rb[j] = Bs[k][tn_ + j];
#pragma unroll
            for (int i = 0; i < 4; i++)
#pragma unroll
                for (int j = 0; j < 4; j++) acc[i][j] += ra[i] * rb[j];
        }
        __syncthreads();
    }

#pragma unroll
    for (int i = 0; i < 4; i++)
#pragma unroll
        for (int j = 0; j < 4; j++) Cs[tm_ + i][tn_ + j] = acc[i][j];
    __syncthreads();

    for (int e = tid; e < 64 * 16; e += 256) {
        int bl = e / 16, dd = e % 16;
        int b = b0 + bl, d = d0 + dd;
        const float* xr = xg + (size_t)b * (4 * DD);
        float gi = Cs[bl][dd]      + xr[d];
        float gf = Cs[bl][16 + dd] + xr[DD + d];
        float gg = Cs[bl][32 + dd] + xr[2 * DD + d];
        float go = Cs[bl][48 + dd] + xr[3 * DD + d];
        size_t idx = (size_t)b * DD + d;
        float m2 = sigmoidf_(gf) * m[idx] + sigmoidf_(gi) * tanhf(gg);
        float tm2 = tanhf(m2);
        m[idx] = m2;
        h_out[idx] = sigmoidf_(go) * tm2;
        tm_out[idx] = tm2;
    }
}

// ---------------- small helpers ----------------
__global__ void mean_kernel(const float* __restrict__ x, float* __restrict__ mean)
{
    int idx = blockIdx.x * blockDim.x + threadIdx.x;
    if (idx >= BB * CC) return;
    int b = idx / CC, c = idx % CC;
    float acc = 0.f;
    const float* p = x + (size_t)b * NN * CC + c;
#pragma unroll 7
    for (int n = 0; n < NN; n++) acc += p[(size_t)n * CC];
    mean[idx] = acc * (1.f / (float)NN);
}

__global__ void we_build(const int* __restrict__ target, const float* __restrict__ emb,
                         float* __restrict__ we)
{
    int idx = blockIdx.x * blockDim.x + threadIdx.x;
    if (idx >= RR * EE) return;
    int e = idx & (EE - 1);
    int tb = idx >> 9;
    int b = tb % BB, t = tb / BB;
    float v = 0.f;
    if (t > 0) v = emb[(size_t)target[b * TT + (t - 1)] * EE + e];
    we[idx] = v;
}

__global__ void cat_w3(const float* __restrict__ Wb, const float* __restrict__ Whi,
                       const float* __restrict__ Wmi, float* __restrict__ Wcat)
{
    int idx = blockIdx.x * blockDim.x + threadIdx.x;
    if (idx >= 3 * DD * CC) return;
    int r = idx / CC;
    const float* src = (r < DD) ? Wb : (r < 2 * DD) ? Whi : Wmi;
    int rr = (r < DD) ? r : (r < 2 * DD) ? r - DD : r - 2 * DD;
    Wcat[idx] = src[(size_t)rr * CC + (idx % CC)];
}

__global__ void split_init(float* __restrict__ vg, float* __restrict__ h0, float* __restrict__ m0)
{
    int idx = blockIdx.x * blockDim.x + threadIdx.x;
    if (idx >= BB * DD) return;
    int b = idx >> 9, d = idx & (DD - 1);
    const float* row = g_init + (size_t)b * (3 * DD);
    vg[idx] = row[d];
    h0[idx] = row[DD + d];
    m0[idx] = row[2 * DD + d];
}

__global__ void fold_xg(const float* __restrict__ bih, const float* __restrict__ bhh)
{
    int idx = blockIdx.x * blockDim.x + threadIdx.x;
    if (idx >= RR * 4 * DD) return;
    int j = idx % (4 * DD);
    int b = (idx / (4 * DD)) % BB;
    g_xg[idx] += g_vgWih[(size_t)b * 4 * DD + j] + bih[j] + bhh[j];
}

__global__ void fold_xx()
{
    int idx = blockIdx.x * blockDim.x + threadIdx.x;
    if (idx >= RR * DD) return;
    int d = idx & (DD - 1);
    int b = (idx >> 9) % BB;
    g_xx[idx] += g_vgWx[(size_t)b * DD + d];
}

__global__ void gate_a()
{
    int idx = blockIdx.x * blockDim.x + threadIdx.x;
    if (idx >= RR * DD) return;
    g_a[idx] = sigmoidf_(g_xx[idx] + g_G1[idx]) * g_tm[idx];
}

// gH = H @ Wg^T ; sWs = s @ Ws^T  over 2560 rows
__global__ void proj49b(const float* __restrict__ Wg, const float* __restrict__ Ws)
{
    int z = blockIdx.y;
    int idx = blockIdx.x * blockDim.x + threadIdx.x;
    if (idx >= RR * NN) return;
    int r = idx / NN, n = idx % NN;
    const float* a = (z ? g_s : g_H) + (size_t)r * DD;
    const float* w = (z ? Ws : Wg) + (size_t)n * DD;
    float acc = 0.f;
#pragma unroll 8
    for (int k = 0; k < DD; k += 4) {
        float4 av = *reinterpret_cast<const float4*>(a + k);
        float4 wv = *reinterpret_cast<const float4*>(w + k);
        acc += av.x * wv.x + av.y * wv.y + av.z * wv.z + av.w * wv.w;
    }
    (z ? g_sWs : g_gH)[idx] = acc;
}

// attention + context, batched over r = t*128+b (grid RR)
__global__ void attn_batched(const float* __restrict__ wh, float* __restrict__ out_attn)
{
    int r = blockIdx.x;
    int t = r / BB, b = r % BB;
    int tid = threadIdx.x;
    __shared__ float gHs[NN], whs[NN], zs[NN + 1], alphas[NN + 1];
    if (tid < NN) { gHs[tid] = g_gH[(size_t)r * NN + tid]; whs[tid] = wh[tid]; }
    __syncthreads();

    if (tid < NN) {
        const float* zb = g_zbase + ((size_t)b * NN + tid) * NN;
        float acc = 0.f;
        for (int k = 0; k < NN; k++) acc += tanhf(zb[k] + gHs[k]) * whs[k];
        zs[tid] = acc;
    } else if (tid == NN) {
        const float* sw = g_sWs + (size_t)r * NN;
        float acc = 0.f;
        for (int k = 0; k < NN; k++) acc += tanhf(sw[k] + gHs[k]) * whs[k];
        zs[NN] = acc;
    }
    __syncthreads();

    if (tid == 0) {
        float mx = -1e30f;
        for (int i = 0; i <= NN; i++) mx = fmaxf(mx, zs[i]);
        float sum = 0.f;
        for (int i = 0; i <= NN; i++) { float e = expf(zs[i] - mx); alphas[i] = e; sum += e; }
        float inv = 1.f / sum;
        for (int i = 0; i <= NN; i++) alphas[i] *= inv;
    }
    __syncthreads();

    if (tid < NN) out_attn[((size_t)b * TT + t) * NN + tid] = alphas[tid];

    for (int d = tid; d < DD; d += blockDim.x) {
        float acc = alphas[NN] * g_s[(size_t)r * DD + d];
        const float* vf = g_Vf + (size_t)b * NN * DD + d;
#pragma unroll 7
        for (int n = 0; n < NN; n++) acc += alphas[n] * vf[(size_t)n * DD];
        g_ctxH[(size_t)r * DD + d] = acc + g_H[(size_t)r * DD + d];
    }
}

__global__ void logsoftmax_kernel(float* __restrict__ out)
{
    int r = blockIdx.x;           // r = t*128+b
    int t = r / BB, b = r % BB;
    const float* row = g_logits + (size_t)r * VOC;
    __shared__ float red[256];
    float mx = -1e30f;
    for (int v = threadIdx.x; v < VOC; v += 256) mx = fmaxf(mx, row[v]);
    red[threadIdx.x] = mx; __syncthreads();
    for (int s = 128; s > 0; s >>= 1) {
        if (threadIdx.x < s) red[threadIdx.x] = fmaxf(red[threadIdx.x], red[threadIdx.x + s]);
        __syncthreads();
    }
    mx = red[0]; __syncthreads();
    float sum = 0.f;
    for (int v = threadIdx.x; v < VOC; v += 256) sum += expf(row[v] - mx);
    red[threadIdx.x] = sum; __syncthreads();
    for (int s = 128; s > 0; s >>= 1) {
        if (threadIdx.x < s) red[threadIdx.x] += red[threadIdx.x + s];
        __syncthreads();
    }
    float lse = mx + logf(red[0]);
    float* orow = out + ((size_t)b * TT + t) * VOC;
    for (int v = threadIdx.x; v < VOC; v += 256) orow[v] = row[v] - lse;
}

// ---------------- launch helpers ----------------
static inline void gemm_big(const float* A, int lda, const float* Bm, int ldb,
                            const float* bias, float* C, int ldc,
                            int M, int N, int K, int act)
{
    dim3 grid((N + 127) / 128, (M + 127) / 128, 1);
    gemm_nt<128, 128, 16, 8, 8><<<grid, 256>>>(A, lda, Bm, ldb, bias, C, ldc, M, N, K, act, 0, 0, 0);
}

static inline void gemm_mid(const float* A, int lda, const float* Bm, int ldb,
                            const float* bias, float* C, int ldc,
                            int M, int N, int K, int act)
{
    dim3 grid((N + 63) / 64, (M + 127) / 128, 1);
    gemm_nt<128, 64, 16, 8, 4><<<grid, 256>>>(A, lda, Bm, ldb, bias, C, ldc, M, N, K, act, 0, 0, 0);
}

static inline void gemm_small(const float* A, int lda, const float* Bm, int ldb,
                              const float* bias, float* C, int ldc,
                              int M, int N, int K, int act,
                              int batch = 1, long long sA = 0, long long sB = 0, long long sC = 0)
{
    dim3 grid((N + 63) / 64, (M + 63) / 64, batch);
    gemm_nt<64, 64, 16, 4, 4><<<grid, 256>>>(A, lda, Bm, ldb, bias, C, ldc, M, N, K, act, sA, sB, sC);
}

extern "C" void kernel_launch(void* const* d_in, const int* in_sizes, int n_in,
                              void* d_out, int out_size)
{
    const float* image = (const float*)d_in[0];
    const int*   target = (const int*)d_in[1];
    const float* emb = (const float*)d_in[2];
    const float* Wa = (const float*)d_in[3];  const float* ba = (const float*)d_in[4];
    const float* Wb = (const float*)d_in[5];  const float* bb = (const float*)d_in[6];
    const float* Whi = (const float*)d_in[7]; const float* bhi = (const float*)d_in[8];
    const float* Wmi = (const float*)d_in[9]; const float* bmi = (const float*)d_in[10];
    const float* Wih = (const float*)d_in[11]; const float* bih = (const float*)d_in[12];
    const float* Whh = (const float*)d_in[13]; const float* bhh = (const float*)d_in[14];
    const float* Wv = (const float*)d_in[15];
    const float* Wg = (const float*)d_in[16];
    const float* wh = (const float*)d_in[17];
    const float* WH = (const float*)d_in[18];
    const float* Wx = (const float*)d_in[19];
    const float* Wh2 = (const float*)d_in[20];
    const float* Ws = (const float*)d_in[21];
    const float* Wc = (const float*)d_in[22]; const float* bc = (const float*)d_in[23];
    const float* Wfc = (const float*)d_in[24]; const float* bfc = (const float*)d_in[25];
    const float* Wp = (const float*)d_in[26]; const float* bp = (const float*)d_in[27];

    float* out = (float*)d_out;
    float* out_attn = out + (size_t)BB * TT * VOC;

    float *p_mean, *p_Vf, *p_zbase, *p_Wcat, *p_init, *p_vg, *p_m, *p_hseq, *p_tm;
    float *p_we, *p_xg, *p_vgWih, *p_xx, *p_vgWx, *p_G1, *p_a, *p_H, *p_s, *p_ctxH, *p_out, *p_logits;
    cudaGetSymbolAddress((void**)&p_mean, g_mean);
    cudaGetSymbolAddress((void**)&p_Vf, g_Vf);
    cudaGetSymbolAddress((void**)&p_zbase, g_zbase);
    cudaGetSymbolAddress((void**)&p_Wcat, g_Wcat);
    cudaGetSymbolAddress((void**)&p_init, g_init);
    cudaGetSymbolAddress((void**)&p_vg, g_vg);
    cudaGetSymbolAddress((void**)&p_m, g_m);
    cudaGetSymbolAddress((void**)&p_hseq, g_hseq);
    cudaGetSymbolAddress((void**)&p_tm, g_tm);
    cudaGetSymbolAddress((void**)&p_we, g_we);
    cudaGetSymbolAddress((void**)&p_xg, g_xg);
    cudaGetSymbolAddress((void**)&p_vgWih, g_vgWih);
    cudaGetSymbolAddress((void**)&p_xx, g_xx);
    cudaGetSymbolAddress((void**)&p_vgWx, g_vgWx);
    cudaGetSymbolAddress((void**)&p_G1, g_G1);
    cudaGetSymbolAddress((void**)&p_a, g_a);
    cudaGetSymbolAddress((void**)&p_H, g_H);
    cudaGetSymbolAddress((void**)&p_s, g_s);
    cudaGetSymbolAddress((void**)&p_ctxH, g_ctxH);
    cudaGetSymbolAddress((void**)&p_out, g_out);
    cudaGetSymbolAddress((void**)&p_logits, g_logits);

    // ---- precompute ----
    mean_kernel<<<(BB * CC + 255) / 256, 256>>>(image, p_mean);
    gemm_big(image, CC, Wa, CC, ba, p_Vf, DD, BB * NN, DD, CC, 1);           // Vf
    cat_w3<<<(3 * DD * CC + 255) / 256, 256>>>(Wb, Whi, Wmi, p_Wcat);
    // relu(mean @ [Wb;Whi;Wmi]^T + bias) — biases added separately (cat bias)
    {
        // fold biases via gemm bias pointer: build on the fly is messy; biases are
        // bb, bhi, bmi — all zeros arrays in dataset but honor them anyway:
        // do gemm without bias then add in split. Simpler: gemm with no bias, add later.
    }
    gemm_small(p_mean, CC, p_Wcat, CC, nullptr, p_init, 3 * DD, BB, 3 * DD, CC, 0);
    // add biases + relu + split
    {
        // small fused kernel below handles relu(init + bias) split
    }
    // split with biases + relu
    {
        struct {} _;
    }
    // (split_init applies no bias/relu; do it via lambda kernel)
    // -> we instead apply bias+relu inside split kernel variant:
    // For simplicity: add biases and relu here using a dedicated kernel.
    {
        // defined below as split_init_bias
    }
    extern __global__ void split_init_bias(const float*, const float*, const float*,
                                           float*, float*, float*);
    split_init_bias<<<(BB * DD + 255) / 256, 256>>>(bb, bhi, bmi, p_vg, p_hseq, p_m);

    // zbase (batched over B)
    gemm_small(p_Vf, DD, Wv, DD, nullptr, p_zbase, NN, NN, NN, DD, 0,
               BB, (long long)NN * DD, 0, (long long)NN * NN);
    we_build<<<(RR * EE + 255) / 256, 256>>>(target, emb, p_we);

    // x projections (batched over all T)
    gemm_big(p_we, EE, Wih + DD, DD + EE, nullptr, p_xg, 4 * DD, RR, 4 * DD, EE, 0);
    gemm_mid(p_vg, DD, Wih, DD + EE, nullptr, p_vgWih, 4 * DD, BB, 4 * DD, DD, 0);
    gemm_mid(p_we, EE, Wx + DD, DD + EE, nullptr, p_xx, DD, RR, DD, EE, 0);
    gemm_mid(p_vg, DD, Wx, DD + EE, nullptr, p_vgWx, DD, BB, DD, DD, 0);
    fold_xg<<<(RR * 4 * DD + 255) / 256, 256>>>(bih, bhh);
    fold_xx<<<(RR * DD + 255) / 256, 256>>>();

    // ---- sequential recurrence: one fused kernel per step ----
    for (int t = 0; t < TT; t++) {
        dim3 grid(32, 2);
        lstm_step<<<grid, 256>>>(Whh,
                                 p_xg + (size_t)t * BB * 4 * DD,
                                 p_hseq + (size_t)t * BB * DD,
                                 p_m,
                                 p_hseq + (size_t)(t + 1) * BB * DD,
                                 p_tm + (size_t)t * BB * DD);
    }

    // ---- batched epilogue over RR rows ----
    const float* Hp = p_hseq;                  // h_0..h_19
    const float* Hc = p_hseq + (size_t)BB * DD; // h_1..h_20
    gemm_mid(Hp, DD, Wh2, DD, nullptr, p_G1, DD, RR, DD, DD, 0);    // hp@Wh2^T
    gemm_mid(Hc, DD, WH, DD, nullptr, p_H, DD, RR, DD, DD, 1);      // H
    gate_a<<<(RR * DD + 255) / 256, 256>>>();                        // a = sig(xx+G1)*tm
    gemm_mid(p_a, DD, Wc, DD, bc, p_s, DD, RR, DD, DD, 1);          // s
    {
        dim3 grid((RR * NN + 255) / 256, 2);
        proj49b<<<grid, 256>>>(Wg, Ws);
    }
    attn_batched<<<RR, 256>>>(wh, out_attn);
    gemm_mid(p_ctxH, DD, Wfc, DD, bfc, p_out, DD, RR, DD, DD, 2);   // out

    // ---- logits + log_softmax ----
    gemm_big(p_out, DD, Wp, DD, bp, p_logits, VOC, RR, VOC, DD, 0);
    logsoftmax_kernel<<<RR, 256>>>(out);
}

// relu(init + bias) and split into vg / h0 / m0
__global__ void split_init_bias(const float* __restrict__ bb, const float* __restrict__ bhi,
                                const float* __restrict__ bmi,
                                float* __restrict__ vg, float* __restrict__ h0,
                                float* __restrict__ m0)
{
    int idx = blockIdx.x * blockDim.x + threadIdx.x;
    if (idx >= BB * DD) return;
    int b = idx >> 9, d = idx & (DD - 1);
    const float* row = g_init + (size_t)b * (3 * DD);
    vg[idx] = fmaxf(row[d] + bb[d], 0.f);
    h0[idx] = fmaxf(row[DD + d] + bhi[d], 0.f);
    m0[idx] = fmaxf(row[2 * DD + d] + bmi[d], 0.f);
}

// round 4
// speedup vs baseline: 4.5763x; 2.0576x over previous
#include <cuda_runtime.h>
#include <cuda_bf16.h>
#include <math.h>
#include <stdint.h>

#define BB 128
#define NN 49
#define CC 2048
#define DD 512
#define EE 512
#define VOC 10000
#define TT 20
#define RR (TT * BB)

// ---------------- scratch (device globals) ----------------
__device__ float g_mean[BB * CC];
__device__ float g_Vf[BB * NN * DD];
__device__ float g_zbase[BB * NN * NN];
__device__ float g_Wcat[3 * DD * CC];
__device__ float g_bcat[3 * DD];
__device__ float g_init[BB * 3 * DD];
__device__ float g_vg[BB * DD];
__device__ float g_m[BB * DD];
__device__ float g_hseq[(TT + 1) * BB * DD];
__device__ float g_tm[RR * DD];
__device__ float g_xcat[RR * (DD + EE)];
__device__ float g_bsum[4 * DD];
__device__ float g_xg[RR * 4 * DD];
__device__ float g_xx[RR * DD];
__device__ float g_gates[BB * 4 * DD];
__device__ float g_G1[RR * DD];
__device__ float g_a[RR * DD];
__device__ float g_H[RR * DD];
__device__ float g_s[RR * DD];
__device__ float g_gH[RR * NN];
__device__ float g_sWs[RR * NN];
__device__ float g_ctxH[RR * DD];
__device__ float g_out[RR * DD];
__device__ float g_logits[(size_t)RR * VOC];

__device__ __forceinline__ float sigmoidf_(float x) { return 1.f / (1.f + expf(-x)); }

__device__ __forceinline__ uint32_t smem_u32(const void* p) {
    uint32_t a;
    asm("{ .reg .u64 t; cvta.to.shared.u64 t, %1; cvt.u32.u64 %0, t; }" : "=r"(a) : "l"(p));
    return a;
}

__device__ __forceinline__ void cp_async16(uint32_t dst, const void* src, bool pred) {
    int sz = pred ? 16 : 0;
    asm volatile("cp.async.cg.shared.global [%0], [%1], 16, %2;"
                 :: "r"(dst), "l"(src), "r"(sz) : "memory");
}
#define CP_COMMIT() asm volatile("cp.async.commit_group;" ::: "memory")
#define CP_WAIT1()  asm volatile("cp.async.wait_group 1;" ::: "memory")

__device__ __forceinline__ void mma_tf32(float* c, const uint32_t* a, uint32_t b0, uint32_t b1)
{
    asm volatile(
        "mma.sync.aligned.m16n8k8.row.col.f32.tf32.tf32.f32 "
        "{%0,%1,%2,%3}, {%4,%5,%6,%7}, {%8,%9}, {%0,%1,%2,%3};"
        : "+f"(c[0]), "+f"(c[1]), "+f"(c[2]), "+f"(c[3])
        : "r"(a[0]), "r"(a[1]), "r"(a[2]), "r"(a[3]), "r"(b0), "r"(b1));
}

// ==================== tf32 HMMA GEMM ====================
// C[m,n] = sum_k A[m,k]*B[n,k] (+bias, act). M = gridDim.y*128 exactly.
// N guarded; K multiple of 32. act: 0 none, 1 relu, 2 tanh.
#define ASTR 36
#define ABUF (128 * ASTR)            // floats per stage per matrix
#define SMEM_MM (4 * ABUF * 4)       // bytes: A0,A1,B0,B1

__global__ void __launch_bounds__(256, 2) gemm_tf32(
    const float* __restrict__ A, int lda,
    const float* __restrict__ B, int ldb,
    const float* __restrict__ bias,
    float* __restrict__ C, int ldc,
    int N, int K, int act)
{
    extern __shared__ float sm[];
    float* sA[2] = { sm, sm + ABUF };
    float* sB[2] = { sm + 2 * ABUF, sm + 3 * ABUF };
    const uint32_t sA_u[2] = { smem_u32(sA[0]), smem_u32(sA[1]) };
    const uint32_t sB_u[2] = { smem_u32(sB[0]), smem_u32(sB[1]) };

    const int tid = threadIdx.x;
    const int wid = tid >> 5, lane = tid & 31;
    const int g = lane >> 2, tg = lane & 3;
    const int wm = (wid & 3) * 32;       // warp m offset
    const int wn = (wid >> 2) * 64;      // warp n offset
    const int m0 = blockIdx.y * 128;
    const int n0 = blockIdx.x * 128;

    A += (size_t)m0 * lda;

    float acc[2][8][4];
#pragma unroll
    for (int mi = 0; mi < 2; mi++)
#pragma unroll
        for (int ni = 0; ni < 8; ni++)
#pragma unroll
            for (int q = 0; q < 4; q++) acc[mi][ni][q] = 0.f;

    const int KI = K >> 5;

    // prologue: prefetch tile 0 into stage 0
    {
#pragma unroll
        for (int j = 0; j < 4; j++) {
            int pos = tid + j * 256;
            int row = pos >> 3, c4 = pos & 7;
            cp_async16(sA_u[0] + (row * ASTR + c4 * 4) * 4,
                       A + (size_t)row * lda + c4 * 4, true);
        }
#pragma unroll
        for (int j = 0; j < 4; j++) {
            int pos = tid + j * 256;
            int row = pos >> 3, c4 = pos & 7;
            int gn = n0 + row;
            bool ok = gn < N;
            int gs = ok ? gn : (N - 1);
            cp_async16(sB_u[0] + (row * ASTR + c4 * 4) * 4,
                       B + (size_t)gs * ldb + c4 * 4, ok);
        }
        CP_COMMIT();
    }

    for (int i = 0; i < KI; i++) {
        const int cur = i & 1;
        // prefetch tile i+1 into other stage
        if (i + 1 < KI) {
            const int nxt = cur ^ 1;
            const int k0 = (i + 1) << 5;
#pragma unroll
            for (int j = 0; j < 4; j++) {
                int pos = tid + j * 256;
                int row = pos >> 3, c4 = pos & 7;
                cp_async16(sA_u[nxt] + (row * ASTR + c4 * 4) * 4,
                           A + (size_t)row * lda + k0 + c4 * 4, true);
            }
#pragma unroll
            for (int j = 0; j < 4; j++) {
                int pos = tid + j * 256;
                int row = pos >> 3, c4 = pos & 7;
                int gn = n0 + row;
                bool ok = gn < N;
                int gs = ok ? gn : (N - 1);
                cp_async16(sB_u[nxt] + (row * ASTR + c4 * 4) * 4,
                           B + (size_t)gs * ldb + k0 + c4 * 4, ok);
            }
        }
        CP_COMMIT();
        CP_WAIT1();
        __syncthreads();

        const float* As_ = sA[cur];
        const float* Bs_ = sB[cur];
#pragma unroll
        for (int kk = 0; kk < 4; kk++) {
            const int kb = kk * 8;
            uint32_t a[2][4];
#pragma unroll
            for (int mi = 0; mi < 2; mi++) {
                int r = wm + mi * 16 + g;
                a[mi][0] = __float_as_uint(As_[r * ASTR + kb + tg]);
                a[mi][1] = __float_as_uint(As_[(r + 8) * ASTR + kb + tg]);
                a[mi][2] = __float_as_uint(As_[r * ASTR + kb + tg + 4]);
                a[mi][3] = __float_as_uint(As_[(r + 8) * ASTR + kb + tg + 4]);
            }
#pragma unroll
            for (int ni = 0; ni < 8; ni++) {
                int rn = wn + ni * 8 + g;
                uint32_t b0 = __float_as_uint(Bs_[rn * ASTR + kb + tg]);
                uint32_t b1 = __float_as_uint(Bs_[rn * ASTR + kb + tg + 4]);
                mma_tf32(acc[0][ni], a[0], b0, b1);
                mma_tf32(acc[1][ni], a[1], b0, b1);
            }
        }
        __syncthreads();
    }

    // epilogue
#pragma unroll
    for (int mi = 0; mi < 2; mi++) {
#pragma unroll
        for (int ni = 0; ni < 8; ni++) {
            int gr = m0 + wm + mi * 16 + g;
            int gc = n0 + wn + ni * 8 + 2 * tg;
#pragma unroll
            for (int q = 0; q < 4; q++) {
                int r = gr + (q >> 1) * 8;
                int c = gc + (q & 1);
                if (c < N) {
                    float v = acc[mi][ni][q];
                    if (bias) v += bias[c];
                    if (act == 1) v = fmaxf(v, 0.f);
                    else if (act == 2) v = tanhf(v);
                    C[(size_t)r * ldc + c] = v;
                }
            }
        }
    }
}

// ==================== SIMT GEMM (zbase only) ====================
template <int BM, int BN, int BK, int TM, int TN>
__global__ void gemm_nt(const float* __restrict__ A, int lda,
                        const float* __restrict__ Bm, int ldb,
                        const float* __restrict__ bias,
                        float* __restrict__ C, int ldc,
                        int M, int N, int K, int act,
                        long long sA, long long sB, long long sC)
{
    constexpr int THREADS = (BM / TM) * (BN / TN);
    __shared__ float As[BK][BM + 4];
    __shared__ float Bs[BK][BN + 4];

    A += (long long)blockIdx.z * sA;
    Bm += (long long)blockIdx.z * sB;
    C += (long long)blockIdx.z * sC;

    const int tid = threadIdx.x;
    const int bm0 = blockIdx.y * BM;
    const int bn0 = blockIdx.x * BN;
    const int tm = (tid / (BN / TN)) * TM;
    const int tn = (tid % (BN / TN)) * TN;

    float acc[TM][TN];
#pragma unroll
    for (int i = 0; i < TM; i++)
#pragma unroll
        for (int j = 0; j < TN; j++) acc[i][j] = 0.f;

    for (int k0 = 0; k0 < K; k0 += BK) {
#pragma unroll
        for (int i = tid; i < BM * (BK / 4); i += THREADS) {
            int row = i / (BK / 4);
            int kc = i % (BK / 4);
            int gm = bm0 + row;
            int gk = k0 + kc * 4;
            float4 v = make_float4(0.f, 0.f, 0.f, 0.f);
            if (gm < M) v = *reinterpret_cast<const float4*>(A + (size_t)gm * lda + gk);
            As[kc * 4 + 0][row] = v.x; As[kc * 4 + 1][row] = v.y;
            As[kc * 4 + 2][row] = v.z; As[kc * 4 + 3][row] = v.w;
        }
#pragma unroll
        for (int i = tid; i < BN * (BK / 4); i += THREADS) {
            int row = i / (BK / 4);
            int kc = i % (BK / 4);
            int gn = bn0 + row;
            int gk = k0 + kc * 4;
            float4 v = make_float4(0.f, 0.f, 0.f, 0.f);
            if (gn < N) v = *reinterpret_cast<const float4*>(Bm + (size_t)gn * ldb + gk);
            Bs[kc * 4 + 0][row] = v.x; Bs[kc * 4 + 1][row] = v.y;
            Bs[kc * 4 + 2][row] = v.z; Bs[kc * 4 + 3][row] = v.w;
        }
        __syncthreads();
#pragma unroll
        for (int k = 0; k < BK; k++) {
            float ra[TM], rb[TN];
#pragma unroll
            for (int i = 0; i < TM; i++) ra[i] = As[k][tm + i];
#pragma unroll
            for (int j = 0; j < TN; j++) rb[j] = Bs[k][tn + j];
#pragma unroll
            for (int i = 0; i < TM; i++)
#pragma unroll
                for (int j = 0; j < TN; j++) acc[i][j] += ra[i] * rb[j];
        }
        __syncthreads();
    }

#pragma unroll
    for (int i = 0; i < TM; i++) {
        int gm = bm0 + tm + i;
        if (gm >= M) continue;
#pragma unroll
        for (int j = 0; j < TN; j++) {
            int gn = bn0 + tn + j;
            if (gn >= N) continue;
            float v = acc[i][j];
            if (bias) v += bias[gn];
            if (act == 1) v = fmaxf(v, 0.f);
            else if (act == 2) v = tanhf(v);
            C[(size_t)gm * ldc + gn] = v;
        }
    }
}

// ==================== elementwise / small kernels ====================
__global__ void mean_kernel(const float* __restrict__ x, float* __restrict__ mean)
{
    int idx = blockIdx.x * blockDim.x + threadIdx.x;
    if (idx >= BB * CC) return;
    int b = idx / CC, c = idx % CC;
    float acc = 0.f;
    const float* p = x + (size_t)b * NN * CC + c;
#pragma unroll 7
    for (int n = 0; n < NN; n++) acc += p[(size_t)n * CC];
    mean[idx] = acc * (1.f / (float)NN);
}

__global__ void cat_w3(const float* __restrict__ Wb, const float* __restrict__ Whi,
                       const float* __restrict__ Wmi, float* __restrict__ Wcat)
{
    int idx = blockIdx.x * blockDim.x + threadIdx.x;
    if (idx >= 3 * DD * CC) return;
    int r = idx / CC;
    const float* src = (r < DD) ? Wb : (r < 2 * DD) ? Whi : Wmi;
    int rr = (r < DD) ? r : (r < 2 * DD) ? r - DD : r - 2 * DD;
    Wcat[idx] = src[(size_t)rr * CC + (idx % CC)];
}

__global__ void cat_bias3(const float* __restrict__ bb, const float* __restrict__ bhi,
                          const float* __restrict__ bmi, float* __restrict__ bcat)
{
    int i = blockIdx.x * blockDim.x + threadIdx.x;
    if (i >= 3 * DD) return;
    bcat[i] = (i < DD) ? bb[i] : (i < 2 * DD) ? bhi[i - DD] : bmi[i - 2 * DD];
}

__global__ void split_init(float* __restrict__ vg, float* __restrict__ h0, float* __restrict__ m0)
{
    int idx = blockIdx.x * blockDim.x + threadIdx.x;
    if (idx >= BB * DD) return;
    int b = idx >> 9, d = idx & (DD - 1);
    const float* row = g_init + (size_t)b * (3 * DD);
    vg[idx] = row[d];
    h0[idx] = row[DD + d];
    m0[idx] = row[2 * DD + d];
}

__global__ void xcat_build(const int* __restrict__ target, const float* __restrict__ emb)
{
    int idx = blockIdx.x * blockDim.x + threadIdx.x;
    if (idx >= RR * (DD + EE)) return;
    int c = idx & 1023;
    int r = idx >> 10;
    int b = r % BB, t = r / BB;
    float v;
    if (c < DD) {
        v = g_vg[(size_t)b * DD + c];
    } else {
        v = 0.f;
        if (t > 0) v = emb[(size_t)target[b * TT + (t - 1)] * EE + (c - DD)];
    }
    g_xcat[idx] = v;
}

__global__ void bias_sum(const float* __restrict__ bih, const float* __restrict__ bhh)
{
    int i = blockIdx.x * blockDim.x + threadIdx.x;
    if (i < 4 * DD) g_bsum[i] = bih[i] + bhh[i];
}

__global__ void lstm_elem(const float* __restrict__ xg_t,
                          float* __restrict__ m,
                          float* __restrict__ h_out,
                          float* __restrict__ tm_out)
{
    int idx = blockIdx.x * blockDim.x + threadIdx.x;
    if (idx >= BB * DD) return;
    int b = idx >> 9, d = idx & (DD - 1);
    const float* gr = g_gates + (size_t)b * (4 * DD);
    const float* xr = xg_t + (size_t)b * (4 * DD);
    float gi = gr[d] + xr[d];
    float gf = gr[DD + d] + xr[DD + d];
    float gg = gr[2 * DD + d] + xr[2 * DD + d];
    float go = gr[3 * DD + d] + xr[3 * DD + d];
    float m2 = sigmoidf_(gf) * m[idx] + sigmoidf_(gi) * tanhf(gg);
    float tm2 = tanhf(m2);
    m[idx] = m2;
    h_out[idx] = sigmoidf_(go) * tm2;
    tm_out[idx] = tm2;
}

__global__ void gate_a()
{
    int idx = blockIdx.x * blockDim.x + threadIdx.x;
    if (idx >= RR * DD) return;
    g_a[idx] = sigmoidf_(g_xx[idx] + g_G1[idx]) * g_tm[idx];
}

__global__ void proj49b(const float* __restrict__ Wg, const float* __restrict__ Ws)
{
    int z = blockIdx.y;
    int idx = blockIdx.x * blockDim.x + threadIdx.x;
    if (idx >= RR * NN) return;
    int r = idx / NN, n = idx % NN;
    const float* a = (z ? g_s : g_H) + (size_t)r * DD;
    const float* w = (z ? Ws : Wg) + (size_t)n * DD;
    float acc = 0.f;
#pragma unroll 8
    for (int k = 0; k < DD; k += 4) {
        float4 av = *reinterpret_cast<const float4*>(a + k);
        float4 wv = *reinterpret_cast<const float4*>(w + k);
        acc += av.x * wv.x + av.y * wv.y + av.z * wv.z + av.w * wv.w;
    }
    (z ? g_sWs : g_gH)[idx] = acc;
}

__global__ void attn_batched(const float* __restrict__ wh, float* __restrict__ out_attn)
{
    int r = blockIdx.x;
    int t = r / BB, b = r % BB;
    int tid = threadIdx.x;
    __shared__ float gHs[NN], whs[NN], zs[NN + 1], alphas[NN + 1];
    if (tid < NN) { gHs[tid] = g_gH[(size_t)r * NN + tid]; whs[tid] = wh[tid]; }
    __syncthreads();

    if (tid < NN) {
        const float* zb = g_zbase + ((size_t)b * NN + tid) * NN;
        float acc = 0.f;
        for (int k = 0; k < NN; k++) acc += tanhf(zb[k] + gHs[k]) * whs[k];
        zs[tid] = acc;
    } else if (tid == NN) {
        const float* sw = g_sWs + (size_t)r * NN;
        float acc = 0.f;
        for (int k = 0; k < NN; k++) acc += tanhf(sw[k] + gHs[k]) * whs[k];
        zs[NN] = acc;
    }
    __syncthreads();

    if (tid == 0) {
        float mx = -1e30f;
        for (int i = 0; i <= NN; i++) mx = fmaxf(mx, zs[i]);
        float sum = 0.f;
        for (int i = 0; i <= NN; i++) { float e = expf(zs[i] - mx); alphas[i] = e; sum += e; }
        float inv = 1.f / sum;
        for (int i = 0; i <= NN; i++) alphas[i] *= inv;
    }
    __syncthreads();

    if (tid < NN) out_attn[((size_t)b * TT + t) * NN + tid] = alphas[tid];

    for (int d = tid; d < DD; d += blockDim.x) {
        float acc = alphas[NN] * g_s[(size_t)r * DD + d];
        const float* vf = g_Vf + (size_t)b * NN * DD + d;
#pragma unroll 7
        for (int n = 0; n < NN; n++) acc += alphas[n] * vf[(size_t)n * DD];
        g_ctxH[(size_t)r * DD + d] = acc + g_H[(size_t)r * DD + d];
    }
}

__global__ void logsoftmax_kernel(float* __restrict__ out)
{
    int r = blockIdx.x;
    int t = r / BB, b = r % BB;
    const float* row = g_logits + (size_t)r * VOC;
    __shared__ float red[256];
    float mx = -1e30f;
    for (int v = threadIdx.x; v < VOC; v += 256) mx = fmaxf(mx, row[v]);
    red[threadIdx.x] = mx; __syncthreads();
    for (int s = 128; s > 0; s >>= 1) {
        if (threadIdx.x < s) red[threadIdx.x] = fmaxf(red[threadIdx.x], red[threadIdx.x + s]);
        __syncthreads();
    }
    mx = red[0]; __syncthreads();
    float sum = 0.f;
    for (int v = threadIdx.x; v < VOC; v += 256) sum += expf(row[v] - mx);
    red[threadIdx.x] = sum; __syncthreads();
    for (int s = 128; s > 0; s >>= 1) {
        if (threadIdx.x < s) red[threadIdx.x] += red[threadIdx.x + s];
        __syncthreads();
    }
    float lse = mx + logf(red[0]);
    float* orow = out + ((size_t)b * TT + t) * VOC;
    for (int v = threadIdx.x; v < VOC; v += 256) orow[v] = row[v] - lse;
}

// ==================== host ====================
static inline void tc(const float* A, int lda, const float* B, int ldb,
                      const float* bias, float* C, int ldc,
                      int Mtiles, int N, int K, int act)
{
    dim3 grid((N + 127) / 128, Mtiles);
    gemm_tf32<<<grid, 256, SMEM_MM>>>(A, lda, B, ldb, bias, C, ldc, N, K, act);
}

extern "C" void kernel_launch(void* const* d_in, const int* in_sizes, int n_in,
                              void* d_out, int out_size)
{
    const float* image = (const float*)d_in[0];
    const int*   target = (const int*)d_in[1];
    const float* emb = (const float*)d_in[2];
    const float* Wa = (const float*)d_in[3];  const float* ba = (const float*)d_in[4];
    const float* Wb = (const float*)d_in[5];  const float* bb = (const float*)d_in[6];
    const float* Whi = (const float*)d_in[7]; const float* bhi = (const float*)d_in[8];
    const float* Wmi = (const float*)d_in[9]; const float* bmi = (const float*)d_in[10];
    const float* Wih = (const float*)d_in[11]; const float* bih = (const float*)d_in[12];
    const float* Whh = (const float*)d_in[13]; const float* bhh = (const float*)d_in[14];
    const float* Wv = (const float*)d_in[15];
    const float* Wg = (const float*)d_in[16];
    const float* wh = (const float*)d_in[17];
    const float* WH = (const float*)d_in[18];
    const float* Wx = (const float*)d_in[19];
    const float* Wh2 = (const float*)d_in[20];
    const float* Ws = (const float*)d_in[21];
    const float* Wc = (const float*)d_in[22]; const float* bc = (const float*)d_in[23];
    const float* Wfc = (const float*)d_in[24]; const float* bfc = (const float*)d_in[25];
    const float* Wp = (const float*)d_in[26]; const float* bp = (const float*)d_in[27];

    float* out = (float*)d_out;
    float* out_attn = out + (size_t)BB * TT * VOC;

    static int smem_set = 0;
    if (!smem_set) {
        cudaFuncSetAttribute(gemm_tf32, cudaFuncAttributeMaxDynamicSharedMemorySize, SMEM_MM);
        smem_set = 1;
    }

    float *p_mean, *p_Vf, *p_zbase, *p_Wcat, *p_bcat, *p_vg, *p_m, *p_hseq, *p_tm;
    float *p_xcat, *p_bsum, *p_xg, *p_xx, *p_gates, *p_G1, *p_a, *p_H, *p_s, *p_ctxH, *p_out, *p_logits, *p_init;
    cudaGetSymbolAddress((void**)&p_mean, g_mean);
    cudaGetSymbolAddress((void**)&p_Vf, g_Vf);
    cudaGetSymbolAddress((void**)&p_zbase, g_zbase);
    cudaGetSymbolAddress((void**)&p_Wcat, g_Wcat);
    cudaGetSymbolAddress((void**)&p_bcat, g_bcat);
    cudaGetSymbolAddress((void**)&p_init, g_init);
    cudaGetSymbolAddress((void**)&p_vg, g_vg);
    cudaGetSymbolAddress((void**)&p_m, g_m);
    cudaGetSymbolAddress((void**)&p_hseq, g_hseq);
    cudaGetSymbolAddress((void**)&p_tm, g_tm);
    cudaGetSymbolAddress((void**)&p_xcat, g_xcat);
    cudaGetSymbolAddress((void**)&p_bsum, g_bsum);
    cudaGetSymbolAddress((void**)&p_xg, g_xg);
    cudaGetSymbolAddress((void**)&p_xx, g_xx);
    cudaGetSymbolAddress((void**)&p_gates, g_gates);
    cudaGetSymbolAddress((void**)&p_G1, g_G1);
    cudaGetSymbolAddress((void**)&p_a, g_a);
    cudaGetSymbolAddress((void**)&p_H, g_H);
    cudaGetSymbolAddress((void**)&p_s, g_s);
    cudaGetSymbolAddress((void**)&p_ctxH, g_ctxH);
    cudaGetSymbolAddress((void**)&p_out, g_out);
    cudaGetSymbolAddress((void**)&p_logits, g_logits);

    // ---- precompute ----
    mean_kernel<<<(BB * CC + 255) / 256, 256>>>(image, p_mean);
    // Vf = relu(image @ Wa^T + ba): M=6272, N=512, K=2048
    tc(image, CC, Wa, CC, ba, p_Vf, DD, BB * NN / 128, DD, CC, 1);
    cat_w3<<<(3 * DD * CC + 255) / 256, 256>>>(Wb, Whi, Wmi, p_Wcat);
    cat_bias3<<<(3 * DD + 255) / 256, 256>>>(bb, bhi, bmi, p_bcat);
    // init = relu(mean @ Wcat^T + bcat): M=128, N=1536, K=2048
    tc(p_mean, CC, p_Wcat, CC, p_bcat, p_init, 3 * DD, 1, 3 * DD, CC, 1);
    split_init<<<(BB * DD + 255) / 256, 256>>>(p_vg, p_hseq, p_m);
    // zbase (batched over B, tiny tiles -> SIMT)
    {
        dim3 grid(1, 1, BB);
        gemm_nt<64, 64, 16, 4, 4><<<grid, 256>>>(p_Vf, DD, Wv, DD, nullptr, p_zbase, NN,
                                                 NN, NN, DD, 0,
                                                 (long long)NN * DD, 0, (long long)NN * NN);
    }
    xcat_build<<<(RR * (DD + EE) + 255) / 256, 256>>>(target, emb);
    bias_sum<<<(4 * DD + 255) / 256, 256>>>(bih, bhh);
    // xg = xcat @ Wih^T + (bih+bhh): M=2560, N=2048, K=1024
    tc(p_xcat, DD + EE, Wih, DD + EE, p_bsum, p_xg, 4 * DD, RR / 128, 4 * DD, DD + EE, 0);
    // xx = xcat @ Wx^T: M=2560, N=512, K=1024
    tc(p_xcat, DD + EE, Wx, DD + EE, nullptr, p_xx, DD, RR / 128, DD, DD + EE, 0);

    // ---- sequential recurrence ----
    for (int t = 0; t < TT; t++) {
        tc(p_hseq + (size_t)t * BB * DD, DD, Whh, DD, nullptr, p_gates, 4 * DD, 1, 4 * DD, DD, 0);
        lstm_elem<<<(BB * DD + 255) / 256, 256>>>(p_xg + (size_t)t * BB * 4 * DD,
                                                  p_m,
                                                  p_hseq + (size_t)(t + 1) * BB * DD,
                                                  p_tm + (size_t)t * BB * DD);
    }

    // ---- batched epilogue over RR rows ----
    const float* Hp = p_hseq;
    const float* Hc = p_hseq + (size_t)BB * DD;
    tc(Hp, DD, Wh2, DD, nullptr, p_G1, DD, RR / 128, DD, DD, 0);
    tc(Hc, DD, WH, DD, nullptr, p_H, DD, RR / 128, DD, DD, 1);
    gate_a<<<(RR * DD + 255) / 256, 256>>>();
    tc(p_a, DD, Wc, DD, bc, p_s, DD, RR / 128, DD, DD, 1);
    {
        dim3 grid((RR * NN + 255) / 256, 2);
        proj49b<<<grid, 256>>>(Wg, Ws);
    }
    attn_batched<<<RR, 256>>>(wh, out_attn);
    tc(p_ctxH, DD, Wfc, DD, bfc, p_out, DD, RR / 128, DD, DD, 2);

    // ---- logits + log_softmax ----
    tc(p_out, DD, Wp, DD, bp, p_logits, VOC, RR / 128, VOC, DD, 0);
    logsoftmax_kernel<<<RR, 256>>>(out);
}

// round 5
// speedup vs baseline: 5.6858x; 1.2425x over previous
#include <cuda_runtime.h>
#include <cuda_bf16.h>
#include <math.h>
#include <stdint.h>

#define BB 128
#define NN 49
#define CC 2048
#define DD 512
#define EE 512
#define VOC 10000
#define TT 20
#define RR (TT * BB)

typedef __nv_bfloat16 bf16;
typedef __nv_bfloat162 bf162;

// ---------------- fp32 scratch ----------------
__device__ float g_Vf[BB * NN * DD];
__device__ float g_zbase[BB * NN * NN];
__device__ float g_bcat[3 * DD];
__device__ float g_init[BB * 3 * DD];
__device__ float g_vg[BB * DD];
__device__ float g_m[BB * DD];
__device__ float g_tm[RR * DD];
__device__ float g_bsum[4 * DD];
__device__ float g_xg[RR * 4 * DD];
__device__ float g_xx[RR * DD];
__device__ float g_gates[BB * 4 * DD];
__device__ float g_G1[RR * DD];
__device__ float g_H[RR * DD];
__device__ float g_s[RR * DD];
__device__ float g_gH[RR * NN];
__device__ float g_sWs[RR * NN];
__device__ float g_out[RR * DD];
__device__ float g_logits[(size_t)RR * VOC];

// ---------------- bf16 scratch (GEMM operands) ----------------
__device__ __align__(16) bf16 g_image_bf[BB * NN * CC];
__device__ __align__(16) bf16 g_Wa_bf[DD * CC];
__device__ __align__(16) bf16 g_mean_bf[BB * CC];
__device__ __align__(16) bf16 g_Wcat_bf[3 * DD * CC];
__device__ __align__(16) bf16 g_xcat_bf[RR * (DD + EE)];
__device__ __align__(16) bf16 g_Wih_bf[4 * DD * (DD + EE)];
__device__ __align__(16) bf16 g_Wx_bf[DD * (DD + EE)];
__device__ __align__(16) bf16 g_Whh_bf[4 * DD * DD];
__device__ __align__(16) bf16 g_Wh2_bf[DD * DD];
__device__ __align__(16) bf16 g_WH_bf[DD * DD];
__device__ __align__(16) bf16 g_Wc_bf[DD * DD];
__device__ __align__(16) bf16 g_Wfc_bf[DD * DD];
__device__ __align__(16) bf16 g_Wp_bf[VOC * DD];
__device__ __align__(16) bf16 g_hseq_bf[(TT + 1) * BB * DD];
__device__ __align__(16) bf16 g_a_bf[RR * DD];
__device__ __align__(16) bf16 g_ctxH_bf[RR * DD];
__device__ __align__(16) bf16 g_out_bf[RR * DD];

__device__ __forceinline__ float sigmoidf_(float x) { return 1.f / (1.f + expf(-x)); }

__device__ __forceinline__ uint32_t smem_u32(const void* p) {
    uint32_t a;
    asm("{ .reg .u64 t; cvta.to.shared.u64 t, %1; cvt.u32.u64 %0, t; }" : "=r"(a) : "l"(p));
    return a;
}

__device__ __forceinline__ void cp_async16(uint32_t dst, const void* src, bool pred) {
    int sz = pred ? 16 : 0;
    asm volatile("cp.async.cg.shared.global [%0], [%1], 16, %2;"
                 :: "r"(dst), "l"(src), "r"(sz) : "memory");
}
#define CP_COMMIT() asm volatile("cp.async.commit_group;" ::: "memory")
#define CP_WAIT1()  asm volatile("cp.async.wait_group 1;" ::: "memory")

__device__ __forceinline__ void mma_bf16(float* c, const uint32_t* a, uint32_t b0, uint32_t b1)
{
    asm volatile(
        "mma.sync.aligned.m16n8k16.row.col.f32.bf16.bf16.f32 "
        "{%0,%1,%2,%3}, {%4,%5,%6,%7}, {%8,%9}, {%0,%1,%2,%3};"
        : "+f"(c[0]), "+f"(c[1]), "+f"(c[2]), "+f"(c[3])
        : "r"(a[0]), "r"(a[1]), "r"(a[2]), "r"(a[3]), "r"(b0), "r"(b1));
}

// ==================== bf16 HMMA GEMM ====================
#define ASTR 40
#define ABUF (128 * ASTR)
#define SMEM_MM (4 * ABUF * 2)

__global__ void __launch_bounds__(256, 2) gemm_bf(
    const bf16* __restrict__ A, int lda,
    const bf16* __restrict__ B, int ldb,
    const float* __restrict__ bias,
    float* __restrict__ C, bf16* __restrict__ Cb, int ldc,
    int N, int K, int act)
{
    extern __shared__ bf16 sm[];
    bf16* sA[2] = { sm, sm + ABUF };
    bf16* sB[2] = { sm + 2 * ABUF, sm + 3 * ABUF };
    const uint32_t sA_u[2] = { smem_u32(sA[0]), smem_u32(sA[1]) };
    const uint32_t sB_u[2] = { smem_u32(sB[0]), smem_u32(sB[1]) };

    const int tid = threadIdx.x;
    const int wid = tid >> 5, lane = tid & 31;
    const int g = lane >> 2, tg = lane & 3;
    const int wm = (wid & 3) * 32;
    const int wn = (wid >> 2) * 64;
    const int m0 = blockIdx.y * 128;
    const int n0 = blockIdx.x * 128;

    A += (size_t)m0 * lda;

    float acc[2][8][4];
#pragma unroll
    for (int mi = 0; mi < 2; mi++)
#pragma unroll
        for (int ni = 0; ni < 8; ni++)
#pragma unroll
            for (int q = 0; q < 4; q++) acc[mi][ni][q] = 0.f;

    const int KI = K >> 5;
    const int r_ld = tid >> 2;
    const int c16 = tid & 3;

    {
#pragma unroll
        for (int j = 0; j < 2; j++) {
            int row = r_ld + j * 64;
            cp_async16(sA_u[0] + (row * ASTR + c16 * 8) * 2,
                       A + (size_t)row * lda + c16 * 8, true);
        }
#pragma unroll
        for (int j = 0; j < 2; j++) {
            int row = r_ld + j * 64;
            int gn = n0 + row;
            bool ok = gn < N;
            int gs = ok ? gn : (N - 1);
            cp_async16(sB_u[0] + (row * ASTR + c16 * 8) * 2,
                       B + (size_t)gs * ldb + c16 * 8, ok);
        }
        CP_COMMIT();
    }

    for (int i = 0; i < KI; i++) {
        const int cur = i & 1;
        if (i + 1 < KI) {
            const int nxt = cur ^ 1;
            const int k0 = (i + 1) << 5;
#pragma unroll
            for (int j = 0; j < 2; j++) {
                int row = r_ld + j * 64;
                cp_async16(sA_u[nxt] + (row * ASTR + c16 * 8) * 2,
                           A + (size_t)row * lda + k0 + c16 * 8, true);
            }
#pragma unroll
            for (int j = 0; j < 2; j++) {
                int row = r_ld + j * 64;
                int gn = n0 + row;
                bool ok = gn < N;
                int gs = ok ? gn : (N - 1);
                cp_async16(sB_u[nxt] + (row * ASTR + c16 * 8) * 2,
                           B + (size_t)gs * ldb + k0 + c16 * 8, ok);
            }
        }
        CP_COMMIT();
        CP_WAIT1();
        __syncthreads();

        const uint32_t* As_ = reinterpret_cast<const uint32_t*>(sA[cur]);
        const uint32_t* Bs_ = reinterpret_cast<const uint32_t*>(sB[cur]);
#pragma unroll
        for (int kk = 0; kk < 2; kk++) {
            const int kw = kk * 8;   // word col base (16 bf16 = 8 words)
            uint32_t a[2][4];
#pragma unroll
            for (int mi = 0; mi < 2; mi++) {
                int r = wm + mi * 16 + g;
                a[mi][0] = As_[r * 20 + kw + tg];
                a[mi][1] = As_[(r + 8) * 20 + kw + tg];
                a[mi][2] = As_[r * 20 + kw + 4 + tg];
                a[mi][3] = As_[(r + 8) * 20 + kw + 4 + tg];
            }
#pragma unroll
            for (int ni = 0; ni < 8; ni++) {
                int rn = wn + ni * 8 + g;
                uint32_t b0 = Bs_[rn * 20 + kw + tg];
                uint32_t b1 = Bs_[rn * 20 + kw + 4 + tg];
                mma_bf16(acc[0][ni], a[0], b0, b1);
                mma_bf16(acc[1][ni], a[1], b0, b1);
            }
        }
        __syncthreads();
    }

#pragma unroll
    for (int mi = 0; mi < 2; mi++) {
#pragma unroll
        for (int ni = 0; ni < 8; ni++) {
            int gr = m0 + wm + mi * 16 + g;
            int gc = n0 + wn + ni * 8 + 2 * tg;
#pragma unroll
            for (int q = 0; q < 4; q++) {
                int r = gr + (q >> 1) * 8;
                int c = gc + (q & 1);
                if (c < N) {
                    float v = acc[mi][ni][q];
                    if (bias) v += bias[c];
                    if (act == 1) v = fmaxf(v, 0.f);
                    else if (act == 2) v = tanhf(v);
                    C[(size_t)r * ldc + c] = v;
                    if (Cb) Cb[(size_t)r * ldc + c] = __float2bfloat16_rn(v);
                }
            }
        }
    }
}

// ==================== SIMT GEMM (zbase only) ====================
template <int BM, int BN, int BK, int TM, int TN>
__global__ void gemm_nt(const float* __restrict__ A, int lda,
                        const float* __restrict__ Bm, int ldb,
                        float* __restrict__ C, int ldc,
                        int M, int N, int K,
                        long long sA, long long sB, long long sC)
{
    constexpr int THREADS = (BM / TM) * (BN / TN);
    __shared__ float As[BK][BM + 4];
    __shared__ float Bs[BK][BN + 4];

    A += (long long)blockIdx.z * sA;
    Bm += (long long)blockIdx.z * sB;
    C += (long long)blockIdx.z * sC;

    const int tid = threadIdx.x;
    const int bm0 = blockIdx.y * BM;
    const int bn0 = blockIdx.x * BN;
    const int tm = (tid / (BN / TN)) * TM;
    const int tn = (tid % (BN / TN)) * TN;

    float acc[TM][TN];
#pragma unroll
    for (int i = 0; i < TM; i++)
#pragma unroll
        for (int j = 0; j < TN; j++) acc[i][j] = 0.f;

    for (int k0 = 0; k0 < K; k0 += BK) {
#pragma unroll
        for (int i = tid; i < BM * (BK / 4); i += THREADS) {
            int row = i / (BK / 4);
            int kc = i % (BK / 4);
            int gm = bm0 + row;
            int gk = k0 + kc * 4;
            float4 v = make_float4(0.f, 0.f, 0.f, 0.f);
            if (gm < M) v = *reinterpret_cast<const float4*>(A + (size_t)gm * lda + gk);
            As[kc * 4 + 0][row] = v.x; As[kc * 4 + 1][row] = v.y;
            As[kc * 4 + 2][row] = v.z; As[kc * 4 + 3][row] = v.w;
        }
#pragma unroll
        for (int i = tid; i < BN * (BK / 4); i += THREADS) {
            int row = i / (BK / 4);
            int kc = i % (BK / 4);
            int gn = bn0 + row;
            int gk = k0 + kc * 4;
            float4 v = make_float4(0.f, 0.f, 0.f, 0.f);
            if (gn < N) v = *reinterpret_cast<const float4*>(Bm + (size_t)gn * ldb + gk);
            Bs[kc * 4 + 0][row] = v.x; Bs[kc * 4 + 1][row] = v.y;
            Bs[kc * 4 + 2][row] = v.z; Bs[kc * 4 + 3][row] = v.w;
        }
        __syncthreads();
#pragma unroll
        for (int k = 0; k < BK; k++) {
            float ra[TM], rb[TN];
#pragma unroll
            for (int i = 0; i < TM; i++) ra[i] = As[k][tm + i];
#pragma unroll
            for (int j = 0; j < TN; j++) rb[j] = Bs[k][tn + j];
#pragma unroll
            for (int i = 0; i < TM; i++)
#pragma unroll
                for (int j = 0; j < TN; j++) acc[i][j] += ra[i] * rb[j];
        }
        __syncthreads();
    }

#pragma unroll
    for (int i = 0; i < TM; i++) {
        int gm = bm0 + tm + i;
        if (gm >= M) continue;
#pragma unroll
        for (int j = 0; j < TN; j++) {
            int gn = bn0 + tn + j;
            if (gn >= N) continue;
            C[(size_t)gm * ldc + gn] = acc[i][j];
        }
    }
}

// ==================== small kernels ====================
__global__ void f2bf(const float* __restrict__ in, bf16* __restrict__ out, int n4)
{
    int i = blockIdx.x * blockDim.x + threadIdx.x;
    if (i >= n4) return;
    float4 v = reinterpret_cast<const float4*>(in)[i];
    bf162* o = reinterpret_cast<bf162*>(out) + i * 2;
    o[0] = __floats2bfloat162_rn(v.x, v.y);
    o[1] = __floats2bfloat162_rn(v.z, v.w);
}

__global__ void mean_kernel(const float* __restrict__ x, bf16* __restrict__ mean_bf)
{
    int idx = blockIdx.x * blockDim.x + threadIdx.x;
    if (idx >= BB * CC) return;
    int b = idx / CC, c = idx % CC;
    float acc = 0.f;
    const float* p = x + (size_t)b * NN * CC + c;
#pragma unroll 7
    for (int n = 0; n < NN; n++) acc += p[(size_t)n * CC];
    mean_bf[idx] = __float2bfloat16_rn(acc * (1.f / (float)NN));
}

__global__ void cat_w3(const float* __restrict__ Wb, const float* __restrict__ Whi,
                       const float* __restrict__ Wmi, bf16* __restrict__ Wcat)
{
    int idx = blockIdx.x * blockDim.x + threadIdx.x;
    if (idx >= 3 * DD * CC) return;
    int r = idx / CC;
    const float* src = (r < DD) ? Wb : (r < 2 * DD) ? Whi : Wmi;
    int rr = (r < DD) ? r : (r < 2 * DD) ? r - DD : r - 2 * DD;
    Wcat[idx] = __float2bfloat16_rn(src[(size_t)rr * CC + (idx % CC)]);
}

__global__ void cat_bias3(const float* __restrict__ bb, const float* __restrict__ bhi,
                          const float* __restrict__ bmi, float* __restrict__ bcat)
{
    int i = blockIdx.x * blockDim.x + threadIdx.x;
    if (i >= 3 * DD) return;
    bcat[i] = (i < DD) ? bb[i] : (i < 2 * DD) ? bhi[i - DD] : bmi[i - 2 * DD];
}

__global__ void split_init(float* __restrict__ vg, bf16* __restrict__ h0,
                           float* __restrict__ m0)
{
    int idx = blockIdx.x * blockDim.x + threadIdx.x;
    if (idx >= BB * DD) return;
    int b = idx >> 9, d = idx & (DD - 1);
    const float* row = g_init + (size_t)b * (3 * DD);
    vg[idx] = row[d];
    h0[idx] = __float2bfloat16_rn(row[DD + d]);
    m0[idx] = row[2 * DD + d];
}

__global__ void xcat_build(const int* __restrict__ target, const float* __restrict__ emb)
{
    int idx = blockIdx.x * blockDim.x + threadIdx.x;
    if (idx >= RR * (DD + EE)) return;
    int c = idx & 1023;
    int r = idx >> 10;
    int b = r % BB, t = r / BB;
    float v;
    if (c < DD) {
        v = g_vg[(size_t)b * DD + c];
    } else {
        v = 0.f;
        if (t > 0) v = emb[(size_t)target[b * TT + (t - 1)] * EE + (c - DD)];
    }
    g_xcat_bf[idx] = __float2bfloat16_rn(v);
}

__global__ void bias_sum(const float* __restrict__ bih, const float* __restrict__ bhh)
{
    int i = blockIdx.x * blockDim.x + threadIdx.x;
    if (i < 4 * DD) g_bsum[i] = bih[i] + bhh[i];
}

__global__ void lstm_elem(const float* __restrict__ xg_t,
                          float* __restrict__ m,
                          bf16* __restrict__ h_out,
                          float* __restrict__ tm_out)
{
    int idx = blockIdx.x * blockDim.x + threadIdx.x;
    if (idx >= BB * DD) return;
    int b = idx >> 9, d = idx & (DD - 1);
    const float* gr = g_gates + (size_t)b * (4 * DD);
    const float* xr = xg_t + (size_t)b * (4 * DD);
    float gi = gr[d] + xr[d];
    float gf = gr[DD + d] + xr[DD + d];
    float gg = gr[2 * DD + d] + xr[2 * DD + d];
    float go = gr[3 * DD + d] + xr[3 * DD + d];
    float m2 = sigmoidf_(gf) * m[idx] + sigmoidf_(gi) * tanhf(gg);
    float tm2 = tanhf(m2);
    m[idx] = m2;
    h_out[idx] = __float2bfloat16_rn(sigmoidf_(go) * tm2);
    tm_out[idx] = tm2;
}

__global__ void gate_a()
{
    int idx = blockIdx.x * blockDim.x + threadIdx.x;
    if (idx >= RR * DD) return;
    g_a_bf[idx] = __float2bfloat16_rn(sigmoidf_(g_xx[idx] + g_G1[idx]) * g_tm[idx]);
}

__global__ void proj49b(const float* __restrict__ Wg, const float* __restrict__ Ws)
{
    int z = blockIdx.y;
    int idx = blockIdx.x * blockDim.x + threadIdx.x;
    if (idx >= RR * NN) return;
    int r = idx / NN, n = idx % NN;
    const float* a = (z ? g_s : g_H) + (size_t)r * DD;
    const float* w = (z ? Ws : Wg) + (size_t)n * DD;
    float acc = 0.f;
#pragma unroll 8
    for (int k = 0; k < DD; k += 4) {
        float4 av = *reinterpret_cast<const float4*>(a + k);
        float4 wv = *reinterpret_cast<const float4*>(w + k);
        acc += av.x * wv.x + av.y * wv.y + av.z * wv.z + av.w * wv.w;
    }
    (z ? g_sWs : g_gH)[idx] = acc;
}

__global__ void attn_batched(const float* __restrict__ wh, float* __restrict__ out_attn)
{
    int r = blockIdx.x;
    int t = r / BB, b = r % BB;
    int tid = threadIdx.x;
    __shared__ float gHs[NN], whs[NN], zs[NN + 1], alphas[NN + 1];
    if (tid < NN) { gHs[tid] = g_gH[(size_t)r * NN + tid]; whs[tid] = wh[tid]; }
    __syncthreads();

    if (tid < NN) {
        const float* zb = g_zbase + ((size_t)b * NN + tid) * NN;
        float acc = 0.f;
        for (int k = 0; k < NN; k++) acc += tanhf(zb[k] + gHs[k]) * whs[k];
        zs[tid] = acc;
    } else if (tid == NN) {
        const float* sw = g_sWs + (size_t)r * NN;
        float acc = 0.f;
        for (int k = 0; k < NN; k++) acc += tanhf(sw[k] + gHs[k]) * whs[k];
        zs[NN] = acc;
    }
    __syncthreads();

    if (tid == 0) {
        float mx = -1e30f;
        for (int i = 0; i <= NN; i++) mx = fmaxf(mx, zs[i]);
        float sum = 0.f;
        for (int i = 0; i <= NN; i++) { float e = expf(zs[i] - mx); alphas[i] = e; sum += e; }
        float inv = 1.f / sum;
        for (int i = 0; i <= NN; i++) alphas[i] *= inv;
    }
    __syncthreads();

    if (tid < NN) out_attn[((size_t)b * TT + t) * NN + tid] = alphas[tid];

    for (int d = tid; d < DD; d += blockDim.x) {
        float acc = alphas[NN] * g_s[(size_t)r * DD + d];
        const float* vf = g_Vf + (size_t)b * NN * DD + d;
#pragma unroll 7
        for (int n = 0; n < NN; n++) acc += alphas[n] * vf[(size_t)n * DD];
        g_ctxH_bf[(size_t)r * DD + d] =
            __float2bfloat16_rn(acc + g_H[(size_t)r * DD + d]);
    }
}

__global__ void logsoftmax_kernel(float* __restrict__ out)
{
    int r = blockIdx.x;
    int t = r / BB, b = r % BB;
    const float* row = g_logits + (size_t)r * VOC;
    __shared__ float red[256];
    float mx = -1e30f;
    for (int v = threadIdx.x; v < VOC; v += 256) mx = fmaxf(mx, row[v]);
    red[threadIdx.x] = mx; __syncthreads();
    for (int s = 128; s > 0; s >>= 1) {
        if (threadIdx.x < s) red[threadIdx.x] = fmaxf(red[threadIdx.x], red[threadIdx.x + s]);
        __syncthreads();
    }
    mx = red[0]; __syncthreads();
    float sum = 0.f;
    for (int v = threadIdx.x; v < VOC; v += 256) sum += expf(row[v] - mx);
    red[threadIdx.x] = sum; __syncthreads();
    for (int s = 128; s > 0; s >>= 1) {
        if (threadIdx.x < s) red[threadIdx.x] += red[threadIdx.x + s];
        __syncthreads();
    }
    float lse = mx + logf(red[0]);
    float* orow = out + ((size_t)b * TT + t) * VOC;
    for (int v = threadIdx.x; v < VOC; v += 256) orow[v] = row[v] - lse;
}

// ==================== host ====================
static inline void tc(const bf16* A, int lda, const bf16* B, int ldb,
                      const float* bias, float* C, bf16* Cb, int ldc,
                      int Mtiles, int N, int K, int act)
{
    dim3 grid((N + 127) / 128, Mtiles);
    gemm_bf<<<grid, 256, SMEM_MM>>>(A, lda, B, ldb, bias, C, Cb, ldc, N, K, act);
}

static inline void conv(const float* in, bf16* out, int n)
{
    int n4 = n / 4;
    f2bf<<<(n4 + 255) / 256, 256>>>(in, out, n4);
}

extern "C" void kernel_launch(void* const* d_in, const int* in_sizes, int n_in,
                              void* d_out, int out_size)
{
    const float* image = (const float*)d_in[0];
    const int*   target = (const int*)d_in[1];
    const float* emb = (const float*)d_in[2];
    const float* Wa = (const float*)d_in[3];  const float* ba = (const float*)d_in[4];
    const float* Wb = (const float*)d_in[5];  const float* bb = (const float*)d_in[6];
    const float* Whi = (const float*)d_in[7]; const float* bhi = (const float*)d_in[8];
    const float* Wmi = (const float*)d_in[9]; const float* bmi = (const float*)d_in[10];
    const float* Wih = (const float*)d_in[11]; const float* bih = (const float*)d_in[12];
    const float* Whh = (const float*)d_in[13]; const float* bhh = (const float*)d_in[14];
    const float* Wv = (const float*)d_in[15];
    const float* Wg = (const float*)d_in[16];
    const float* wh = (const float*)d_in[17];
    const float* WH = (const float*)d_in[18];
    const float* Wx = (const float*)d_in[19];
    const float* Wh2 = (const float*)d_in[20];
    const float* Ws = (const float*)d_in[21];
    const float* Wc = (const float*)d_in[22]; const float* bc = (const float*)d_in[23];
    const float* Wfc = (const float*)d_in[24]; const float* bfc = (const float*)d_in[25];
    const float* Wp = (const float*)d_in[26]; const float* bp = (const float*)d_in[27];

    float* out = (float*)d_out;
    float* out_attn = out + (size_t)BB * TT * VOC;

    float *p_Vf, *p_zbase, *p_bcat, *p_vg, *p_m, *p_tm, *p_bsum, *p_xg, *p_xx, *p_gates;
    float *p_G1, *p_H, *p_s, *p_out, *p_logits, *p_init;
    bf16 *pb_image, *pb_Wa, *pb_mean, *pb_Wcat, *pb_xcat, *pb_Wih, *pb_Wx, *pb_Whh;
    bf16 *pb_Wh2, *pb_WH, *pb_Wc, *pb_Wfc, *pb_Wp, *pb_hseq, *pb_a, *pb_ctxH, *pb_out;
    cudaGetSymbolAddress((void**)&p_Vf, g_Vf);
    cudaGetSymbolAddress((void**)&p_zbase, g_zbase);
    cudaGetSymbolAddress((void**)&p_bcat, g_bcat);
    cudaGetSymbolAddress((void**)&p_init, g_init);
    cudaGetSymbolAddress((void**)&p_vg, g_vg);
    cudaGetSymbolAddress((void**)&p_m, g_m);
    cudaGetSymbolAddress((void**)&p_tm, g_tm);
    cudaGetSymbolAddress((void**)&p_bsum, g_bsum);
    cudaGetSymbolAddress((void**)&p_xg, g_xg);
    cudaGetSymbolAddress((void**)&p_xx, g_xx);
    cudaGetSymbolAddress((void**)&p_gates, g_gates);
    cudaGetSymbolAddress((void**)&p_G1, g_G1);
    cudaGetSymbolAddress((void**)&p_H, g_H);
    cudaGetSymbolAddress((void**)&p_s, g_s);
    cudaGetSymbolAddress((void**)&p_out, g_out);
    cudaGetSymbolAddress((void**)&p_logits, g_logits);
    cudaGetSymbolAddress((void**)&pb_image, g_image_bf);
    cudaGetSymbolAddress((void**)&pb_Wa, g_Wa_bf);
    cudaGetSymbolAddress((void**)&pb_mean, g_mean_bf);
    cudaGetSymbolAddress((void**)&pb_Wcat, g_Wcat_bf);
    cudaGetSymbolAddress((void**)&pb_xcat, g_xcat_bf);
    cudaGetSymbolAddress((void**)&pb_Wih, g_Wih_bf);
    cudaGetSymbolAddress((void**)&pb_Wx, g_Wx_bf);
    cudaGetSymbolAddress((void**)&pb_Whh, g_Whh_bf);
    cudaGetSymbolAddress((void**)&pb_Wh2, g_Wh2_bf);
    cudaGetSymbolAddress((void**)&pb_WH, g_WH_bf);
    cudaGetSymbolAddress((void**)&pb_Wc, g_Wc_bf);
    cudaGetSymbolAddress((void**)&pb_Wfc, g_Wfc_bf);
    cudaGetSymbolAddress((void**)&pb_Wp, g_Wp_bf);
    cudaGetSymbolAddress((void**)&pb_hseq, g_hseq_bf);
    cudaGetSymbolAddress((void**)&pb_a, g_a_bf);
    cudaGetSymbolAddress((void**)&pb_ctxH, g_ctxH_bf);
    cudaGetSymbolAddress((void**)&pb_out, g_out_bf);

    // ---- conversions ----
    conv(image, pb_image, BB * NN * CC);
    conv(Wa, pb_Wa, DD * CC);
    conv(Wih, pb_Wih, 4 * DD * (DD + EE));
    conv(Wx, pb_Wx, DD * (DD + EE));
    conv(Whh, pb_Whh, 4 * DD * DD);
    conv(Wh2, pb_Wh2, DD * DD);
    conv(WH, pb_WH, DD * DD);
    conv(Wc, pb_Wc, DD * DD);
    conv(Wfc, pb_Wfc, DD * DD);
    conv(Wp, pb_Wp, VOC * DD);

    // ---- precompute ----
    mean_kernel<<<(BB * CC + 255) / 256, 256>>>(image, pb_mean);
    tc(pb_image, CC, pb_Wa, CC, ba, p_Vf, nullptr, DD, BB * NN / 128, DD, CC, 1);
    cat_w3<<<(3 * DD * CC + 255) / 256, 256>>>(Wb, Whi, Wmi, pb_Wcat);
    cat_bias3<<<(3 * DD + 255) / 256, 256>>>(bb, bhi, bmi, p_bcat);
    tc(pb_mean, CC, pb_Wcat, CC, p_bcat, p_init, nullptr, 3 * DD, 1, 3 * DD, CC, 1);
    split_init<<<(BB * DD + 255) / 256, 256>>>(p_vg, pb_hseq, p_m);
    {
        dim3 grid(1, 1, BB);
        gemm_nt<64, 64, 16, 4, 4><<<grid, 256>>>(p_Vf, DD, Wv, DD, p_zbase, NN,
                                                 NN, NN, DD,
                                                 (long long)NN * DD, 0, (long long)NN * NN);
    }
    xcat_build<<<(RR * (DD + EE) + 255) / 256, 256>>>(target, emb);
    bias_sum<<<(4 * DD + 255) / 256, 256>>>(bih, bhh);
    tc(pb_xcat, DD + EE, pb_Wih, DD + EE, p_bsum, p_xg, nullptr, 4 * DD, RR / 128, 4 * DD, DD + EE, 0);
    tc(pb_xcat, DD + EE, pb_Wx, DD + EE, nullptr, p_xx, nullptr, DD, RR / 128, DD, DD + EE, 0);

    // ---- sequential recurrence ----
    for (int t = 0; t < TT; t++) {
        tc(pb_hseq + (size_t)t * BB * DD, DD, pb_Whh, DD, nullptr, p_gates, nullptr,
           4 * DD, 1, 4 * DD, DD, 0);
        lstm_elem<<<(BB * DD + 255) / 256, 256>>>(p_xg + (size_t)t * BB * 4 * DD,
                                                  p_m,
                                                  pb_hseq + (size_t)(t + 1) * BB * DD,
                                                  p_tm + (size_t)t * BB * DD);
    }

    // ---- batched epilogue over RR rows ----
    const bf16* Hp = pb_hseq;
    const bf16* Hc = pb_hseq + (size_t)BB * DD;
    tc(Hp, DD, pb_Wh2, DD, nullptr, p_G1, nullptr, DD, RR / 128, DD, DD, 0);
    tc(Hc, DD, pb_WH, DD, nullptr, p_H, nullptr, DD, RR / 128, DD, DD, 1);
    gate_a<<<(RR * DD + 255) / 256, 256>>>();
    tc(pb_a, DD, pb_Wc, DD, bc, p_s, nullptr, DD, RR / 128, DD, DD, 1);
    {
        dim3 grid((RR * NN + 255) / 256, 2);
        proj49b<<<grid, 256>>>(Wg, Ws);
    }
    attn_batched<<<RR, 256>>>(wh, out_attn);
    tc(pb_ctxH, DD, pb_Wfc, DD, bfc, p_out, pb_out, DD, RR / 128, DD, DD, 2);

    // ---- logits + log_softmax ----
    tc(pb_out, DD, pb_Wp, DD, bp, p_logits, nullptr, VOC, RR / 128, VOC, DD, 0);
    logsoftmax_kernel<<<RR, 256>>>(out);
}